// round 2
// baseline (speedup 1.0000x reference)
#include <cuda_runtime.h>
#include <cuda_bf16.h>
#include <math.h>

#define NBATCH 32
#define NNODE  512
#define NHEAD  8
#define FHID   16

// ---------------- scratch (device globals; no allocations) ----------------
__device__ float    g_hp1[NBATCH*NHEAD*NNODE*FHID];   // 8 MB
__device__ float    g_as [NBATCH*NHEAD*NNODE];
__device__ float    g_Es [NBATCH*NHEAD*NNODE];
__device__ float    g_Fs [NBATCH*NHEAD*NNODE];
__device__ float    g_ad [NBATCH*NHEAD*NNODE];
__device__ float    g_Ed [NBATCH*NHEAD*NNODE];
__device__ float    g_Fd [NBATCH*NHEAD*NNODE];
__device__ unsigned g_bits[NBATCH*NNODE*16];          // 1 MB bit-packed adjacency
__device__ float    g_x  [NBATCH*NNODE*128];          // 8 MB layer-2 input
__device__ float    g_hp2[NBATCH*NNODE*64];           // 4 MB
__device__ float    g_as2[NBATCH*NNODE];
__device__ float    g_ad2[NBATCH*NNODE];

// ---------------- packed f32x2 helpers (sm_103a) ----------------
static __device__ __forceinline__ unsigned long long pk2(float lo, float hi) {
    unsigned long long r;
    asm("mov.b64 %0,{%1,%2};" : "=l"(r) : "f"(lo), "f"(hi));
    return r;
}
static __device__ __forceinline__ void upk2(unsigned long long v, float& lo, float& hi) {
    asm("mov.b64 {%0,%1},%2;" : "=f"(lo), "=f"(hi) : "l"(v));
}
static __device__ __forceinline__ unsigned long long fma2(unsigned long long a,
                                                          unsigned long long b,
                                                          unsigned long long c) {
    unsigned long long d;
    asm("fma.rn.f32x2 %0,%1,%2,%3;" : "=l"(d) : "l"(a), "l"(b), "l"(c));
    return d;
}

// ---------------- K0: bit-pack adjacency ----------------
__global__ void k_pack(const int* __restrict__ adj) {
    int idx = blockIdx.x * 256 + threadIdx.x;
    unsigned m = __ballot_sync(0xffffffffu, adj[idx] > 0);
    if ((threadIdx.x & 31) == 0) g_bits[idx >> 5] = m;
}

// ---------------- K1: layer-1 projection + tanh + exp tables ----------------
// grid (4, 32), block 256, dynamic smem ~97.5 KB
__global__ void __launch_bounds__(256) k_proj1(
    const float* __restrict__ features, const float* __restrict__ line_emb,
    const int*   __restrict__ v_types,  const float* __restrict__ w1,
    const float* __restrict__ a_src1,   const float* __restrict__ a_dst1)
{
    extern __shared__ float sm1[];
    float* ws  = sm1;          // 24576: [t][f][h*16+o]
    float* asr = ws + 24576;   // 128
    float* ads = asr + 128;    // 128
    float* emb = ads + 128;    // 128 (2 nodes x 64)
    int tid = threadIdx.x, b = blockIdx.y, bx = blockIdx.x;

    for (int i = tid; i < 24576; i += 256) {
        int o = i & 15, f = (i >> 4) & 63, h = (i >> 10) & 7, t = i >> 13;
        ws[(t * 64 + f) * 128 + h * 16 + o] = w1[i];
    }
    if (tid < 128) { asr[tid] = a_src1[tid]; ads[tid] = a_dst1[tid]; }

    int sub = tid >> 7, l = tid & 127, o = l & 15, h = l >> 4;
    for (int it = 0; it < 64; it++) {
        int nbase = bx * 128 + it * 2;
        __syncthreads();
        if (tid < 128) {
            int s2 = tid >> 6, f = tid & 63, nl = nbase + s2;
            emb[tid] = (f < 32) ? features[(b * NNODE + nl) * 32 + f]
                                : line_emb[(b * NNODE + nl) * 32 + f - 32];
        }
        __syncthreads();
        int n = nbase + sub;
        int ty = v_types[b * NNODE + n];
        const float* wr = ws + ty * 64 * 128 + l;
        const float* ev = emb + sub * 64;
        float acc = 0.f;
        #pragma unroll
        for (int f = 0; f < 64; f++) acc = fmaf(ev[f], wr[f * 128], acc);
        g_hp1[((b * NHEAD + h) * NNODE + n) * FHID + o] = acc;
        float th = tanhf(acc);
        float ps = th * asr[l], pd = th * ads[l];
        #pragma unroll
        for (int off = 8; off; off >>= 1) {
            ps += __shfl_xor_sync(0xffffffffu, ps, off);
            pd += __shfl_xor_sync(0xffffffffu, pd, off);
        }
        if (o == 0) {
            int ai = (b * NHEAD + h) * NNODE + n;
            g_as[ai] = ps; g_Es[ai] = expf(ps); g_Fs[ai] = expf(0.2f * ps);
            g_ad[ai] = pd; g_Ed[ai] = expf(pd); g_Fd[ai] = expf(0.2f * pd);
        }
    }
}

// ---------------- K2: attention softmax + attn1 store ----------------
// grid (8, 32) = (h, b), 512 threads; thread t = column m
__global__ void __launch_bounds__(512) k_attn1(float* __restrict__ attn_out) {
    __shared__ float    as_s[512], Es_s[512], Fs_s[512];
    __shared__ unsigned bits_s[8192];
    __shared__ float    wsum[64], inv_s[4];
    int t = threadIdx.x, h = blockIdx.x, b = blockIdx.y;
    int bh = b * NHEAD + h;

    for (int i = t; i < 8192; i += 512) bits_s[i] = g_bits[b * 8192 + i];
    as_s[t] = g_as[bh * 512 + t];
    Es_s[t] = g_Es[bh * 512 + t];
    Fs_s[t] = g_Fs[bh * 512 + t];
    float ad = g_ad[bh * 512 + t];
    float Ed = g_Ed[bh * 512 + t];
    float Fd = g_Fd[bh * 512 + t];
    int lane = t & 31, wid = t >> 5;
    float* ob = attn_out + (size_t)bh * 512 * 512;
    __syncthreads();

    for (int n0 = 0; n0 < 512; n0 += 4) {
        float num[4];
        #pragma unroll
        for (int r = 0; r < 4; r++) {
            int n = n0 + r;
            float s = as_s[n] + ad;
            float e = (s >= 0.f) ? Es_s[n] * Ed : Fs_s[n] * Fd;
            unsigned w = bits_s[n * 16 + wid];
            e = ((w >> lane) & 1u) ? e : 0.f;
            num[r] = e;
            float sum = e;
            #pragma unroll
            for (int off = 16; off; off >>= 1)
                sum += __shfl_xor_sync(0xffffffffu, sum, off);
            if (lane == 0) wsum[r * 16 + wid] = sum;
        }
        __syncthreads();
        if (t < 64) {
            float v = wsum[t];
            #pragma unroll
            for (int off = 8; off; off >>= 1)
                v += __shfl_xor_sync(0xffffffffu, v, off);
            if ((t & 15) == 0) inv_s[t >> 4] = 1.f / v;
        }
        __syncthreads();
        #pragma unroll
        for (int r = 0; r < 4; r++)
            ob[(size_t)(n0 + r) * 512 + t] = num[r] * inv_s[r];
    }
}

// ---------------- K3: out1 = attn @ h_prime + b1, elu, transpose -> g_x ----------------
// grid (4, 8, 32) = (ntile, h, b), block 256, dynamic smem ~48.5 KB
__global__ void __launch_bounds__(256) k_gemm1(const float* __restrict__ attn,
                                               const float* __restrict__ b1) {
    extern __shared__ float sm3[];
    float* hps = sm3;          // 8192: hp[m][o]
    float* at  = sm3 + 8192;   // 128*33 padded attn tile
    int tid = threadIdx.x;
    int nt = blockIdx.x, h = blockIdx.y, b = blockIdx.z;
    int bh = b * NHEAD + h;

    for (int i = tid; i < 8192; i += 256) hps[i] = g_hp1[bh * 8192 + i];

    int rl = tid >> 1, oh = tid & 1;
    unsigned long long z = pk2(0.f, 0.f), a01 = z, a23 = z, a45 = z, a67 = z;
    const float* ab = attn + ((size_t)bh * 512 + nt * 128) * 512;

    for (int mc = 0; mc < 16; mc++) {
        __syncthreads();
        for (int i = tid; i < 4096; i += 256) {
            int r = i >> 5, mm = i & 31;
            at[r * 33 + mm] = ab[(size_t)r * 512 + mc * 32 + mm];
        }
        __syncthreads();
        const unsigned long long* hq =
            (const unsigned long long*)(hps + mc * 32 * 16 + oh * 8);
        const float* ar = at + rl * 33;
        #pragma unroll
        for (int mm = 0; mm < 32; mm++) {
            unsigned long long pa = pk2(ar[mm], ar[mm]);
            a01 = fma2(pa, hq[mm * 8 + 0], a01);
            a23 = fma2(pa, hq[mm * 8 + 1], a23);
            a45 = fma2(pa, hq[mm * 8 + 2], a45);
            a67 = fma2(pa, hq[mm * 8 + 3], a67);
        }
    }
    float v[8];
    upk2(a01, v[0], v[1]); upk2(a23, v[2], v[3]);
    upk2(a45, v[4], v[5]); upk2(a67, v[6], v[7]);
    int n = nt * 128 + rl, ob = oh * 8;
    float res[8];
    #pragma unroll
    for (int k = 0; k < 8; k++) {
        float x = v[k] + b1[ob + k];
        res[k] = x > 0.f ? x : expm1f(x);
    }
    float* dst = &g_x[(size_t)(b * 512 + n) * 128 + h * 16 + ob];
    ((float4*)dst)[0] = make_float4(res[0], res[1], res[2], res[3]);
    ((float4*)dst)[1] = make_float4(res[4], res[5], res[6], res[7]);
}

// ---------------- K4: layer-2 projection + attention scalars ----------------
// grid (4, 32), block 256, dynamic smem ~98.6 KB
__global__ void __launch_bounds__(256) k_proj2(
    const int* __restrict__ v_types, const float* __restrict__ w2,
    const float* __restrict__ a_src2, const float* __restrict__ a_dst2)
{
    extern __shared__ float sm4[];
    float* ws  = sm4;          // 24576: already [t][f][o]
    float* asw = ws + 24576;   // 64
    float* adw = asw + 64;     // 64
    float* xv  = adw + 64;     // 512 (4 nodes x 128)
    float* pr  = xv + 512;     // 16
    int tid = threadIdx.x, b = blockIdx.y, bx = blockIdx.x;

    for (int i = tid; i < 24576; i += 256) ws[i] = w2[i];
    if (tid < 64) { asw[tid] = a_src2[tid]; adw[tid] = a_dst2[tid]; }

    int sub = tid >> 6, o = tid & 63, w8 = tid >> 5, lane = tid & 31;
    for (int it = 0; it < 32; it++) {
        int nbase = bx * 128 + it * 4;
        __syncthreads();
        for (int i = tid; i < 512; i += 256)
            xv[i] = g_x[(size_t)(b * 512 + nbase) * 128 + i];
        __syncthreads();
        int n = nbase + sub;
        int ty = v_types[b * 512 + n];
        const float* wp = ws + ty * 8192 + o;
        const float* xp = xv + sub * 128;
        float acc = 0.f;
        #pragma unroll
        for (int f = 0; f < 128; f++) acc = fmaf(xp[f], wp[f * 64], acc);
        g_hp2[(size_t)(b * 512 + n) * 64 + o] = acc;
        float th = tanhf(acc);
        float ps = th * asw[o], pd = th * adw[o];
        #pragma unroll
        for (int off = 16; off; off >>= 1) {
            ps += __shfl_xor_sync(0xffffffffu, ps, off);
            pd += __shfl_xor_sync(0xffffffffu, pd, off);
        }
        if (lane == 0) { pr[w8] = ps; pr[8 + w8] = pd; }
        __syncthreads();
        if (tid < 4) {
            g_as2[b * 512 + nbase + tid] = pr[tid * 2] + pr[tid * 2 + 1];
            g_ad2[b * 512 + nbase + tid] = pr[8 + tid * 2] + pr[8 + tid * 2 + 1];
        }
    }
}

// ---------------- K5: layer-2 rows 0/1 + MLP + log_softmax ----------------
__global__ void __launch_bounds__(256) k_final(
    const float* __restrict__ b2,
    const float* __restrict__ fc1_w, const float* __restrict__ fc1_b,
    const float* __restrict__ fc2_w, const float* __restrict__ fc2_b,
    const float* __restrict__ fc3_w, const float* __restrict__ fc3_b,
    float* __restrict__ out_scores, float* __restrict__ out_vsm)
{
    __shared__ float att2[2 * 512];
    __shared__ float inv[2];
    __shared__ float xrow[128];
    __shared__ float vsm[64], v1[192], v2s[64];
    __shared__ float red[16];
    __shared__ float sc[2];
    int tid = threadIdx.x, b = blockIdx.x;

    float p0 = 0.f, p1 = 0.f;
    for (int r = 0; r < 2; r++) {
        float as = g_as2[b * 512 + r];
        for (int m = tid; m < 512; m += 256) {
            float s = as + g_ad2[b * 512 + m];
            unsigned w = g_bits[b * 8192 + r * 16 + (m >> 5)];
            float e = ((w >> (m & 31)) & 1u) ? expf(s >= 0.f ? s : 0.2f * s) : 0.f;
            att2[r * 512 + m] = e;
            if (r == 0) p0 += e; else p1 += e;
        }
    }
    #pragma unroll
    for (int off = 16; off; off >>= 1) {
        p0 += __shfl_xor_sync(0xffffffffu, p0, off);
        p1 += __shfl_xor_sync(0xffffffffu, p1, off);
    }
    if ((tid & 31) == 0) { red[tid >> 5] = p0; red[8 + (tid >> 5)] = p1; }
    __syncthreads();
    if (tid == 0) {
        float s0 = 0.f, s1 = 0.f;
        for (int i = 0; i < 8; i++) { s0 += red[i]; s1 += red[8 + i]; }
        inv[0] = 1.f / s0; inv[1] = 1.f / s1;
    }
    __syncthreads();
    if (tid < 128) {
        int r = tid >> 6, o = tid & 63;
        float a0 = 0.f, a1 = 0.f, a2 = 0.f, a3 = 0.f;
        const float* hp = &g_hp2[(size_t)b * 512 * 64 + o];
        const float* av = &att2[r * 512];
        for (int m = 0; m < 512; m += 4) {
            a0 = fmaf(av[m],     hp[(size_t)m * 64],       a0);
            a1 = fmaf(av[m + 1], hp[(size_t)(m + 1) * 64], a1);
            a2 = fmaf(av[m + 2], hp[(size_t)(m + 2) * 64], a2);
            a3 = fmaf(av[m + 3], hp[(size_t)(m + 3) * 64], a3);
        }
        float x = (a0 + a1 + a2 + a3) * inv[r] + b2[o];
        xrow[r * 64 + o] = x > 0.f ? x : expm1f(x);
    }
    __syncthreads();
    if (tid < 64) {
        float vv = xrow[tid] * xrow[64 + tid];
        vsm[tid] = vv;
        out_vsm[b * 64 + tid] = vv;
    }
    __syncthreads();
    if (tid < 192) {
        float acc = fc1_b[tid];
        for (int f = 0; f < 64; f++) acc = fmaf(vsm[f], fc1_w[f * 192 + tid], acc);
        v1[tid] = fmaxf(acc, 0.f);
    }
    __syncthreads();
    if (tid < 64) {
        float acc = fc2_b[tid];
        for (int f = 0; f < 192; f++) acc = fmaf(v1[f], fc2_w[f * 64 + tid], acc);
        v2s[tid] = fmaxf(acc, 0.f);
    }
    __syncthreads();
    if (tid < 2) {
        float acc = fc3_b[tid];
        for (int f = 0; f < 64; f++) acc = fmaf(v2s[f], fc3_w[f * 2 + tid], acc);
        sc[tid] = acc;
    }
    __syncthreads();
    if (tid < 2) {
        float m = fmaxf(sc[0], sc[1]);
        float lse = m + logf(expf(sc[0] - m) + expf(sc[1] - m));
        out_scores[b * 2 + tid] = sc[tid] - lse;
    }
}

// ---------------- launch ----------------
extern "C" void kernel_launch(void* const* d_in, const int* in_sizes, int n_in,
                              void* d_out, int out_size) {
    (void)in_sizes; (void)n_in; (void)out_size;
    const float* features = (const float*)d_in[0];
    const int*   adj      = (const int*)  d_in[1];
    const float* svm      = (const float*)d_in[4]; (void)svm;
    const float* line_emb = (const float*)d_in[5];
    const int*   v_types  = (const int*)  d_in[6];
    const float* w1       = (const float*)d_in[7];
    const float* a_src1   = (const float*)d_in[8];
    const float* a_dst1   = (const float*)d_in[9];
    const float* b1       = (const float*)d_in[10];
    const float* w2       = (const float*)d_in[11];
    const float* a_src2   = (const float*)d_in[12];
    const float* a_dst2   = (const float*)d_in[13];
    const float* b2       = (const float*)d_in[14];
    const float* fc1_w    = (const float*)d_in[15];
    const float* fc1_b    = (const float*)d_in[16];
    const float* fc2_w    = (const float*)d_in[17];
    const float* fc2_b    = (const float*)d_in[18];
    const float* fc3_w    = (const float*)d_in[19];
    const float* fc3_b    = (const float*)d_in[20];

    float* out   = (float*)d_out;
    float* vsm   = out + 64;       // v_sim_mul [32,64]
    float* attn1 = out + 2112;     // attn1 [32,8,512,512]

    cudaFuncSetAttribute(k_proj1, cudaFuncAttributeMaxDynamicSharedMemorySize, 100000);
    cudaFuncSetAttribute(k_gemm1, cudaFuncAttributeMaxDynamicSharedMemorySize, 50000);
    cudaFuncSetAttribute(k_proj2, cudaFuncAttributeMaxDynamicSharedMemorySize, 101000);

    k_pack <<<32768, 256>>>(adj);
    k_proj1<<<dim3(4, 32), 256, 99840>>>(features, line_emb, v_types, w1, a_src1, a_dst1);
    k_attn1<<<dim3(8, 32), 512>>>(attn1);
    k_gemm1<<<dim3(4, 8, 32), 256, 49664>>>(attn1, b1);
    k_proj2<<<dim3(4, 32), 256, 100928>>>(v_types, w2, a_src2, a_dst2);
    k_final<<<32, 256>>>(b2, fc1_w, fc1_b, fc2_w, fc2_b, fc3_w, fc3_b, out, vsm);
}

// round 3
// speedup vs baseline: 1.2683x; 1.2683x over previous
#include <cuda_runtime.h>
#include <cuda_bf16.h>
#include <math.h>

#define NBATCH 32
#define NNODE  512
#define NHEAD  8
#define FHID   16

// ---------------- scratch (device globals; no allocations) ----------------
__device__ float    g_hp1[NBATCH*NHEAD*NNODE*FHID];   // 8 MB
__device__ float    g_as [NBATCH*NHEAD*NNODE];
__device__ float    g_Es [NBATCH*NHEAD*NNODE];
__device__ float    g_Fs [NBATCH*NHEAD*NNODE];
__device__ float    g_ad [NBATCH*NHEAD*NNODE];
__device__ float    g_Ed [NBATCH*NHEAD*NNODE];
__device__ float    g_Fd [NBATCH*NHEAD*NNODE];
__device__ float    g_inv[NBATCH*NHEAD*NNODE];        // per-row 1/sum
__device__ unsigned g_bits[NBATCH*NNODE*16];          // 1 MB bit-packed adjacency
__device__ float    g_x  [NBATCH*NNODE*128];          // 8 MB layer-2 input
__device__ float    g_hp2[NBATCH*NNODE*64];           // 4 MB
__device__ float    g_as2[NBATCH*NNODE];
__device__ float    g_ad2[NBATCH*NNODE];

// ---------------- packed f32x2 helpers (sm_103a) ----------------
static __device__ __forceinline__ unsigned long long pk2(float lo, float hi) {
    unsigned long long r;
    asm("mov.b64 %0,{%1,%2};" : "=l"(r) : "f"(lo), "f"(hi));
    return r;
}
static __device__ __forceinline__ void upk2(unsigned long long v, float& lo, float& hi) {
    asm("mov.b64 {%0,%1},%2;" : "=f"(lo), "=f"(hi) : "l"(v));
}
static __device__ __forceinline__ unsigned long long fma2(unsigned long long a,
                                                          unsigned long long b,
                                                          unsigned long long c) {
    unsigned long long d;
    asm("fma.rn.f32x2 %0,%1,%2,%3;" : "=l"(d) : "l"(a), "l"(b), "l"(c));
    return d;
}

// ---------------- K0: bit-pack adjacency ----------------
__global__ void k_pack(const int* __restrict__ adj) {
    int idx = blockIdx.x * 256 + threadIdx.x;
    unsigned m = __ballot_sync(0xffffffffu, adj[idx] > 0);
    if ((threadIdx.x & 31) == 0) g_bits[idx >> 5] = m;
}

// ---------------- K1: layer-1 projection + tanh + exp tables ----------------
__global__ void __launch_bounds__(256) k_proj1(
    const float* __restrict__ features, const float* __restrict__ line_emb,
    const int*   __restrict__ v_types,  const float* __restrict__ w1,
    const float* __restrict__ a_src1,   const float* __restrict__ a_dst1)
{
    extern __shared__ float sm1[];
    float* ws  = sm1;          // 24576: [t][f][h*16+o]
    float* asr = ws + 24576;   // 128
    float* ads = asr + 128;    // 128
    float* emb = ads + 128;    // 128 (2 nodes x 64)
    int tid = threadIdx.x, b = blockIdx.y, bx = blockIdx.x;

    for (int i = tid; i < 24576; i += 256) {
        int o = i & 15, f = (i >> 4) & 63, h = (i >> 10) & 7, t = i >> 13;
        ws[(t * 64 + f) * 128 + h * 16 + o] = w1[i];
    }
    if (tid < 128) { asr[tid] = a_src1[tid]; ads[tid] = a_dst1[tid]; }

    int sub = tid >> 7, l = tid & 127, o = l & 15, h = l >> 4;
    for (int it = 0; it < 64; it++) {
        int nbase = bx * 128 + it * 2;
        __syncthreads();
        if (tid < 128) {
            int s2 = tid >> 6, f = tid & 63, nl = nbase + s2;
            emb[tid] = (f < 32) ? features[(b * NNODE + nl) * 32 + f]
                                : line_emb[(b * NNODE + nl) * 32 + f - 32];
        }
        __syncthreads();
        int n = nbase + sub;
        int ty = v_types[b * NNODE + n];
        const float* wr = ws + ty * 64 * 128 + l;
        const float* ev = emb + sub * 64;
        float acc = 0.f;
        #pragma unroll
        for (int f = 0; f < 64; f++) acc = fmaf(ev[f], wr[f * 128], acc);
        g_hp1[((b * NHEAD + h) * NNODE + n) * FHID + o] = acc;
        float th = tanhf(acc);
        float ps = th * asr[l], pd = th * ads[l];
        #pragma unroll
        for (int off = 8; off; off >>= 1) {
            ps += __shfl_xor_sync(0xffffffffu, ps, off);
            pd += __shfl_xor_sync(0xffffffffu, pd, off);
        }
        if (o == 0) {
            int ai = (b * NHEAD + h) * NNODE + n;
            g_as[ai] = ps; g_Es[ai] = expf(ps); g_Fs[ai] = expf(0.2f * ps);
            g_ad[ai] = pd; g_Ed[ai] = expf(pd); g_Fd[ai] = expf(0.2f * pd);
        }
    }
}

// ---------------- K2: attention softmax + attn1 store (+ row inv sums) ----------------
__global__ void __launch_bounds__(512) k_attn1(float* __restrict__ attn_out) {
    __shared__ float    as_s[512], Es_s[512], Fs_s[512];
    __shared__ unsigned bits_s[8192];
    __shared__ float    wsum[64], inv_s[4];
    int t = threadIdx.x, h = blockIdx.x, b = blockIdx.y;
    int bh = b * NHEAD + h;

    for (int i = t; i < 8192; i += 512) bits_s[i] = g_bits[b * 8192 + i];
    as_s[t] = g_as[bh * 512 + t];
    Es_s[t] = g_Es[bh * 512 + t];
    Fs_s[t] = g_Fs[bh * 512 + t];
    float ad = g_ad[bh * 512 + t];
    float Ed = g_Ed[bh * 512 + t];
    float Fd = g_Fd[bh * 512 + t];
    int lane = t & 31, wid = t >> 5;
    float* ob = attn_out + (size_t)bh * 512 * 512;
    __syncthreads();

    for (int n0 = 0; n0 < 512; n0 += 4) {
        float num[4];
        #pragma unroll
        for (int r = 0; r < 4; r++) {
            int n = n0 + r;
            float s = as_s[n] + ad;
            float e = (s >= 0.f) ? Es_s[n] * Ed : Fs_s[n] * Fd;
            unsigned w = bits_s[n * 16 + wid];
            e = ((w >> lane) & 1u) ? e : 0.f;
            num[r] = e;
            float sum = e;
            #pragma unroll
            for (int off = 16; off; off >>= 1)
                sum += __shfl_xor_sync(0xffffffffu, sum, off);
            if (lane == 0) wsum[r * 16 + wid] = sum;
        }
        __syncthreads();
        if (t < 64) {
            float v = wsum[t];
            #pragma unroll
            for (int off = 8; off; off >>= 1)
                v += __shfl_xor_sync(0xffffffffu, v, off);
            if ((t & 15) == 0) inv_s[t >> 4] = 1.f / v;
        }
        __syncthreads();
        #pragma unroll
        for (int r = 0; r < 4; r++)
            __stcs(&ob[(size_t)(n0 + r) * 512 + t], num[r] * inv_s[r]);
        if (t < 4) g_inv[bh * 512 + n0 + t] = inv_s[t];
    }
}

// ---------------- K3: out1 = attn @ h_prime (attn RECOMPUTED, no gmem read) ----------------
// grid (2, 8, 32) = (nhalf, h, b), 128 threads, dyn smem 55296 B
__global__ void __launch_bounds__(128) k_gemm1(const float* __restrict__ b1) {
    extern __shared__ float sm3[];
    float*    hp_s   = sm3;                 // 8192 floats [m][o]
    float*    ads    = hp_s + 8192;         // 512
    float*    Eds    = ads + 512;           // 512
    float*    Fds    = Eds + 512;           // 512
    unsigned* bits_s = (unsigned*)(Fds + 512); // 4096 words
    int tid = threadIdx.x;
    int nh = blockIdx.x, h = blockIdx.y, b = blockIdx.z;
    int bh = b * NHEAD + h;
    int n0 = nh * 256;

    for (int i = tid; i < 8192; i += 128) hp_s[i] = g_hp1[bh * 8192 + i];
    for (int i = tid; i < 512; i += 128) {
        ads[i] = g_ad[bh * 512 + i];
        Eds[i] = g_Ed[bh * 512 + i];
        Fds[i] = g_Fd[bh * 512 + i];
    }
    for (int i = tid; i < 4096; i += 128)
        bits_s[i] = g_bits[b * 8192 + n0 * 16 + i];

    int na = n0 + tid * 2, nb = na + 1;
    float as_a = g_as[bh * 512 + na], as_b = g_as[bh * 512 + nb];
    float iva  = g_inv[bh * 512 + na], ivb = g_inv[bh * 512 + nb];
    float Esa = g_Es[bh * 512 + na] * iva, Fsa = g_Fs[bh * 512 + na] * iva;
    float Esb = g_Es[bh * 512 + nb] * ivb, Fsb = g_Fs[bh * 512 + nb] * ivb;
    __syncthreads();

    unsigned long long acc[16];
    unsigned long long z = pk2(0.f, 0.f);
    #pragma unroll
    for (int q = 0; q < 16; q++) acc[q] = z;

    int la = (tid * 2) * 16, lb = la + 16;
    for (int mw = 0; mw < 16; mw++) {
        unsigned wa = bits_s[la + mw], wb = bits_s[lb + mw];
        #pragma unroll 8
        for (int mi = 0; mi < 32; mi++) {
            int m = mw * 32 + mi;
            float ad = ads[m], Ed = Eds[m], Fd = Fds[m];
            float ea = ((as_a + ad) >= 0.f) ? Esa * Ed : Fsa * Fd;
            float eb = ((as_b + ad) >= 0.f) ? Esb * Ed : Fsb * Fd;
            ea = ((wa >> mi) & 1u) ? ea : 0.f;
            eb = ((wb >> mi) & 1u) ? eb : 0.f;
            unsigned long long pa = pk2(ea, ea);
            unsigned long long pb = pk2(eb, eb);
            const unsigned long long* hq = (const unsigned long long*)(hp_s + m * 16);
            #pragma unroll
            for (int q = 0; q < 8; q++) {
                acc[q]     = fma2(pa, hq[q], acc[q]);
                acc[8 + q] = fma2(pb, hq[q], acc[8 + q]);
            }
        }
    }

    float va[16], vb[16];
    #pragma unroll
    for (int q = 0; q < 8; q++) {
        upk2(acc[q],     va[2 * q], va[2 * q + 1]);
        upk2(acc[8 + q], vb[2 * q], vb[2 * q + 1]);
    }
    float ra[16], rb[16];
    #pragma unroll
    for (int k = 0; k < 16; k++) {
        float xa = va[k] + b1[k];
        float xb = vb[k] + b1[k];
        ra[k] = xa > 0.f ? xa : expm1f(xa);
        rb[k] = xb > 0.f ? xb : expm1f(xb);
    }
    float* da = &g_x[(size_t)(b * 512 + na) * 128 + h * 16];
    float* db = &g_x[(size_t)(b * 512 + nb) * 128 + h * 16];
    #pragma unroll
    for (int q = 0; q < 4; q++) {
        ((float4*)da)[q] = make_float4(ra[4*q], ra[4*q+1], ra[4*q+2], ra[4*q+3]);
        ((float4*)db)[q] = make_float4(rb[4*q], rb[4*q+1], rb[4*q+2], rb[4*q+3]);
    }
}

// ---------------- K4: layer-2 projection + attention scalars ----------------
__global__ void __launch_bounds__(256) k_proj2(
    const int* __restrict__ v_types, const float* __restrict__ w2,
    const float* __restrict__ a_src2, const float* __restrict__ a_dst2)
{
    extern __shared__ float sm4[];
    float* ws  = sm4;          // 24576: already [t][f][o]
    float* asw = ws + 24576;   // 64
    float* adw = asw + 64;     // 64
    float* xv  = adw + 64;     // 512 (4 nodes x 128)
    float* pr  = xv + 512;     // 16
    int tid = threadIdx.x, b = blockIdx.y, bx = blockIdx.x;

    for (int i = tid; i < 24576; i += 256) ws[i] = w2[i];
    if (tid < 64) { asw[tid] = a_src2[tid]; adw[tid] = a_dst2[tid]; }

    int sub = tid >> 6, o = tid & 63, w8 = tid >> 5, lane = tid & 31;
    for (int it = 0; it < 32; it++) {
        int nbase = bx * 128 + it * 4;
        __syncthreads();
        for (int i = tid; i < 512; i += 256)
            xv[i] = g_x[(size_t)(b * 512 + nbase) * 128 + i];
        __syncthreads();
        int n = nbase + sub;
        int ty = v_types[b * 512 + n];
        const float* wp = ws + ty * 8192 + o;
        const float* xp = xv + sub * 128;
        float acc = 0.f;
        #pragma unroll
        for (int f = 0; f < 128; f++) acc = fmaf(xp[f], wp[f * 64], acc);
        g_hp2[(size_t)(b * 512 + n) * 64 + o] = acc;
        float th = tanhf(acc);
        float ps = th * asw[o], pd = th * adw[o];
        #pragma unroll
        for (int off = 16; off; off >>= 1) {
            ps += __shfl_xor_sync(0xffffffffu, ps, off);
            pd += __shfl_xor_sync(0xffffffffu, pd, off);
        }
        if (lane == 0) { pr[w8] = ps; pr[8 + w8] = pd; }
        __syncthreads();
        if (tid < 4) {
            g_as2[b * 512 + nbase + tid] = pr[tid * 2] + pr[tid * 2 + 1];
            g_ad2[b * 512 + nbase + tid] = pr[8 + tid * 2] + pr[8 + tid * 2 + 1];
        }
    }
}

// ---------------- K5: layer-2 rows 0/1 + MLP + log_softmax ----------------
__global__ void __launch_bounds__(512) k_final(
    const float* __restrict__ b2,
    const float* __restrict__ fc1_w, const float* __restrict__ fc1_b,
    const float* __restrict__ fc2_w, const float* __restrict__ fc2_b,
    const float* __restrict__ fc3_w, const float* __restrict__ fc3_b,
    float* __restrict__ out_scores, float* __restrict__ out_vsm)
{
    __shared__ float att2[2 * 512];
    __shared__ float inv[2];
    __shared__ float part[512];
    __shared__ float xrow[128];
    __shared__ float vsm[64], v1[192], v2s[64];
    __shared__ float red[32];
    __shared__ float sc[2];
    int tid = threadIdx.x, b = blockIdx.x;
    int lane = tid & 31, wid = tid >> 5;

    // phase 1: att2 rows 0,1 over columns m=tid
    float ad2 = g_ad2[b * 512 + tid];
    unsigned wrd = g_bits[b * 8192 + (tid >> 5)];
    unsigned wrd1 = g_bits[b * 8192 + 16 + (tid >> 5)];
    float as0 = g_as2[b * 512 + 0], as1 = g_as2[b * 512 + 1];
    float s0 = as0 + ad2, s1 = as1 + ad2;
    float e0 = ((wrd  >> lane) & 1u) ? expf(s0 >= 0.f ? s0 : 0.2f * s0) : 0.f;
    float e1 = ((wrd1 >> lane) & 1u) ? expf(s1 >= 0.f ? s1 : 0.2f * s1) : 0.f;
    att2[tid] = e0;
    att2[512 + tid] = e1;
    float p0 = e0, p1 = e1;
    #pragma unroll
    for (int off = 16; off; off >>= 1) {
        p0 += __shfl_xor_sync(0xffffffffu, p0, off);
        p1 += __shfl_xor_sync(0xffffffffu, p1, off);
    }
    if (lane == 0) { red[wid] = p0; red[16 + wid] = p1; }
    __syncthreads();
    if (tid < 32) {
        float v = red[tid];
        #pragma unroll
        for (int off = 8; off; off >>= 1)
            v += __shfl_xor_sync(0xffffffffu, v, off);
        if (tid == 0)  inv[0] = 1.f / v;
        if (tid == 16) inv[1] = 1.f / v;
    }
    __syncthreads();

    // phase 2: xrow[r][o] = (sum_m att2[r][m]*hp2[m][o]) * inv[r] + b2[o], elu
    {
        int r = tid >> 8, o = tid & 63, sub = (tid >> 6) & 3;
        const float* hp = g_hp2 + (size_t)b * 32768 + o;
        const float* av = att2 + r * 512 + sub * 128;
        float a0 = 0.f, a1 = 0.f, a2 = 0.f, a3 = 0.f;
        int mb = sub * 128;
        #pragma unroll 4
        for (int k = 0; k < 128; k += 4) {
            a0 = fmaf(av[k],     hp[(size_t)(mb + k) * 64],     a0);
            a1 = fmaf(av[k + 1], hp[(size_t)(mb + k + 1) * 64], a1);
            a2 = fmaf(av[k + 2], hp[(size_t)(mb + k + 2) * 64], a2);
            a3 = fmaf(av[k + 3], hp[(size_t)(mb + k + 3) * 64], a3);
        }
        part[tid] = (a0 + a1) + (a2 + a3);
    }
    __syncthreads();
    if (tid < 128) {
        int r = tid >> 6, o = tid & 63;
        float x = (part[r * 256 + o] + part[r * 256 + 64 + o] +
                   part[r * 256 + 128 + o] + part[r * 256 + 192 + o]) * inv[r] + b2[o];
        xrow[tid] = x > 0.f ? x : expm1f(x);
    }
    __syncthreads();
    if (tid < 64) {
        float vv = xrow[tid] * xrow[64 + tid];
        vsm[tid] = vv;
        out_vsm[b * 64 + tid] = vv;
    }
    __syncthreads();
    if (tid < 192) {
        float acc = fc1_b[tid];
        for (int f = 0; f < 64; f++) acc = fmaf(vsm[f], fc1_w[f * 192 + tid], acc);
        v1[tid] = fmaxf(acc, 0.f);
    }
    __syncthreads();
    if (tid < 64) {
        float acc = fc2_b[tid];
        for (int f = 0; f < 192; f++) acc = fmaf(v1[f], fc2_w[f * 64 + tid], acc);
        v2s[tid] = fmaxf(acc, 0.f);
    }
    __syncthreads();
    if (tid < 2) {
        float acc = fc3_b[tid];
        for (int f = 0; f < 64; f++) acc = fmaf(v2s[f], fc3_w[f * 2 + tid], acc);
        sc[tid] = acc;
    }
    __syncthreads();
    if (tid < 2) {
        float m = fmaxf(sc[0], sc[1]);
        float lse = m + logf(expf(sc[0] - m) + expf(sc[1] - m));
        out_scores[b * 2 + tid] = sc[tid] - lse;
    }
}

// ---------------- launch ----------------
extern "C" void kernel_launch(void* const* d_in, const int* in_sizes, int n_in,
                              void* d_out, int out_size) {
    (void)in_sizes; (void)n_in; (void)out_size;
    const float* features = (const float*)d_in[0];
    const int*   adj      = (const int*)  d_in[1];
    const float* line_emb = (const float*)d_in[5];
    const int*   v_types  = (const int*)  d_in[6];
    const float* w1       = (const float*)d_in[7];
    const float* a_src1   = (const float*)d_in[8];
    const float* a_dst1   = (const float*)d_in[9];
    const float* b1       = (const float*)d_in[10];
    const float* w2       = (const float*)d_in[11];
    const float* a_src2   = (const float*)d_in[12];
    const float* a_dst2   = (const float*)d_in[13];
    const float* b2       = (const float*)d_in[14];
    const float* fc1_w    = (const float*)d_in[15];
    const float* fc1_b    = (const float*)d_in[16];
    const float* fc2_w    = (const float*)d_in[17];
    const float* fc2_b    = (const float*)d_in[18];
    const float* fc3_w    = (const float*)d_in[19];
    const float* fc3_b    = (const float*)d_in[20];

    float* out   = (float*)d_out;
    float* vsm   = out + 64;       // v_sim_mul [32,64]
    float* attn1 = out + 2112;     // attn1 [32,8,512,512]

    cudaFuncSetAttribute(k_proj1, cudaFuncAttributeMaxDynamicSharedMemorySize, 100000);
    cudaFuncSetAttribute(k_gemm1, cudaFuncAttributeMaxDynamicSharedMemorySize, 56000);
    cudaFuncSetAttribute(k_proj2, cudaFuncAttributeMaxDynamicSharedMemorySize, 101000);

    k_pack <<<32768, 256>>>(adj);
    k_proj1<<<dim3(4, 32), 256, 99840>>>(features, line_emb, v_types, w1, a_src1, a_dst1);
    k_attn1<<<dim3(8, 32), 512>>>(attn1);
    k_gemm1<<<dim3(2, 8, 32), 128, 55296>>>(b1);
    k_proj2<<<dim3(4, 32), 256, 100928>>>(v_types, w2, a_src2, a_dst2);
    k_final<<<32, 512>>>(b2, fc1_w, fc1_b, fc2_w, fc2_b, fc3_w, fc3_b, out, vsm);
}

// round 4
// speedup vs baseline: 1.4218x; 1.1210x over previous
#include <cuda_runtime.h>
#include <cuda_bf16.h>
#include <math.h>

#define NBATCH 32
#define NNODE  512
#define NHEAD  8
#define FHID   16

// ---------------- scratch (device globals; no allocations) ----------------
__device__ float    g_hp1[NBATCH*NHEAD*NNODE*FHID];   // 8 MB
__device__ float    g_as [NBATCH*NHEAD*NNODE];
__device__ float    g_Es [NBATCH*NHEAD*NNODE];
__device__ float    g_Fs [NBATCH*NHEAD*NNODE];
__device__ float    g_ad [NBATCH*NHEAD*NNODE];
__device__ float    g_Ed [NBATCH*NHEAD*NNODE];
__device__ float    g_Fd [NBATCH*NHEAD*NNODE];
__device__ unsigned g_bits[NBATCH*NNODE*16];          // 1 MB bit-packed adjacency
__device__ float    g_x  [NBATCH*NNODE*128];          // 8 MB layer-2 input
__device__ float    g_hp2[NBATCH*NNODE*64];           // 4 MB
__device__ float    g_as2[NBATCH*NNODE];
__device__ float    g_ad2[NBATCH*NNODE];

// ---------------- packed f32x2 helpers (sm_103a) ----------------
static __device__ __forceinline__ unsigned long long pk2(float lo, float hi) {
    unsigned long long r;
    asm("mov.b64 %0,{%1,%2};" : "=l"(r) : "f"(lo), "f"(hi));
    return r;
}
static __device__ __forceinline__ void upk2(unsigned long long v, float& lo, float& hi) {
    asm("mov.b64 {%0,%1},%2;" : "=f"(lo), "=f"(hi) : "l"(v));
}
static __device__ __forceinline__ unsigned long long fma2(unsigned long long a,
                                                          unsigned long long b,
                                                          unsigned long long c) {
    unsigned long long d;
    asm("fma.rn.f32x2 %0,%1,%2,%3;" : "=l"(d) : "l"(a), "l"(b), "l"(c));
    return d;
}

// ---------------- K0: bit-pack adjacency ----------------
__global__ void k_pack(const int* __restrict__ adj) {
    int idx = blockIdx.x * 256 + threadIdx.x;
    unsigned m = __ballot_sync(0xffffffffu, adj[idx] > 0);
    if ((threadIdx.x & 31) == 0) g_bits[idx >> 5] = m;
}

// ---------------- K1: layer-1 projection + tanh + exp tables ----------------
// grid (8, 32), block 256
__global__ void __launch_bounds__(256) k_proj1(
    const float* __restrict__ features, const float* __restrict__ line_emb,
    const int*   __restrict__ v_types,  const float* __restrict__ w1,
    const float* __restrict__ a_src1,   const float* __restrict__ a_dst1)
{
    extern __shared__ float sm1[];
    float* ws  = sm1;          // 24576: [t][f][h*16+o]
    float* asr = ws + 24576;   // 128
    float* ads = asr + 128;    // 128
    float* emb = ads + 128;    // 128 (2 nodes x 64)
    int tid = threadIdx.x, b = blockIdx.y, bx = blockIdx.x;

    for (int i = tid; i < 24576; i += 256) {
        int o = i & 15, f = (i >> 4) & 63, h = (i >> 10) & 7, t = i >> 13;
        ws[(t * 64 + f) * 128 + h * 16 + o] = w1[i];
    }
    if (tid < 128) { asr[tid] = a_src1[tid]; ads[tid] = a_dst1[tid]; }

    int sub = tid >> 7, l = tid & 127, o = l & 15, h = l >> 4;
    for (int it = 0; it < 32; it++) {
        int nbase = bx * 64 + it * 2;
        __syncthreads();
        if (tid < 128) {
            int s2 = tid >> 6, f = tid & 63, nl = nbase + s2;
            emb[tid] = (f < 32) ? features[(b * NNODE + nl) * 32 + f]
                                : line_emb[(b * NNODE + nl) * 32 + f - 32];
        }
        __syncthreads();
        int n = nbase + sub;
        int ty = v_types[b * NNODE + n];
        const float* wr = ws + ty * 64 * 128 + l;
        const float* ev = emb + sub * 64;
        float acc = 0.f;
        #pragma unroll
        for (int f = 0; f < 64; f++) acc = fmaf(ev[f], wr[f * 128], acc);
        g_hp1[((b * NHEAD + h) * NNODE + n) * FHID + o] = acc;
        float th = tanhf(acc);
        float ps = th * asr[l], pd = th * ads[l];
        #pragma unroll
        for (int off = 8; off; off >>= 1) {
            ps += __shfl_xor_sync(0xffffffffu, ps, off);
            pd += __shfl_xor_sync(0xffffffffu, pd, off);
        }
        if (o == 0) {
            int ai = (b * NHEAD + h) * NNODE + n;
            g_as[ai] = ps; g_Es[ai] = expf(ps); g_Fs[ai] = expf(0.2f * ps);
            g_ad[ai] = pd; g_Ed[ai] = expf(pd); g_Fd[ai] = expf(0.2f * pd);
        }
    }
}

// ---------------- K2: FUSED attn softmax + attn1 store + out1 GEMM + elu ----------------
// grid (2, 8, 32) = (nhalf, h, b), 128 threads, dyn smem 57408 B
__global__ void __launch_bounds__(128) k_fuse(const float* __restrict__ b1,
                                              float* __restrict__ attn_out) {
    extern __shared__ float smf[];
    float*    hp_s   = smf;                       // 8192 floats [m][o]
    float4*   tbl    = (float4*)(smf + 8192);     // 512 float4 (ad, Ed, Fd, 0)
    unsigned* bits_s = (unsigned*)(smf + 10240);  // 4096 words, layout [w][r]
    float*    b1s    = smf + 14336;               // 16
    int tid = threadIdx.x;
    int nh = blockIdx.x, h = blockIdx.y, b = blockIdx.z;
    int bh = b * NHEAD + h;
    int n0 = nh * 256;

    for (int i = tid; i < 8192; i += 128) hp_s[i] = g_hp1[bh * 8192 + i];
    for (int i = tid; i < 512; i += 128)
        tbl[i] = make_float4(g_ad[bh * 512 + i], g_Ed[bh * 512 + i],
                             g_Fd[bh * 512 + i], 0.f);
    // bits transposed: bits_s[w*256 + r] = g_bits[b][n0+r][w]
    for (int i = tid; i < 4096; i += 128) {
        int w = i >> 8, r = i & 255;
        bits_s[i] = g_bits[b * 8192 + (n0 + r) * 16 + w];
    }
    if (tid < 16) b1s[tid] = b1[tid];

    int rla = tid * 2, rlb = rla + 1;            // local rows
    int na = n0 + rla, nb = n0 + rlb;
    float as_a = g_as[bh * 512 + na], as_b = g_as[bh * 512 + nb];
    float Es_a = g_Es[bh * 512 + na], Fs_a = g_Fs[bh * 512 + na];
    float Es_b = g_Es[bh * 512 + nb], Fs_b = g_Fs[bh * 512 + nb];
    __syncthreads();

    // ---- pass A: row sums (no shuffles, no barriers) ----
    float SEa = 0.f, SFa = 0.f, SEb = 0.f, SFb = 0.f;
    for (int mw = 0; mw < 16; mw++) {
        unsigned wa = bits_s[mw * 256 + rla];
        unsigned wb = bits_s[mw * 256 + rlb];
        #pragma unroll
        for (int mi = 0; mi < 32; mi++) {
            float4 t = tbl[mw * 32 + mi];
            float sa = as_a + t.x, sb = as_b + t.x;
            bool ba = (wa >> mi) & 1u, bb = (wb >> mi) & 1u;
            SEa += (ba && sa >= 0.f) ? t.y : 0.f;
            SFa += (ba && sa <  0.f) ? t.z : 0.f;
            SEb += (bb && sb >= 0.f) ? t.y : 0.f;
            SFb += (bb && sb <  0.f) ? t.z : 0.f;
        }
    }
    float inva = 1.f / fmaf(Es_a, SEa, Fs_a * SFa);
    float invb = 1.f / fmaf(Es_b, SEb, Fs_b * SFb);
    float Esa = Es_a * inva, Fsa = Fs_a * inva;
    float Esb = Es_b * invb, Fsb = Fs_b * invb;

    // ---- pass B: attn recompute + store + fma2 GEMM ----
    unsigned long long acc[16];
    unsigned long long z = pk2(0.f, 0.f);
    #pragma unroll
    for (int q = 0; q < 16; q++) acc[q] = z;

    float* ob = attn_out + (size_t)bh * 512 * 512;
    for (int mw = 0; mw < 16; mw++) {
        unsigned wa = bits_s[mw * 256 + rla];
        unsigned wb = bits_s[mw * 256 + rlb];
        #pragma unroll
        for (int half = 0; half < 2; half++) {
            float ea16[16], eb16[16];
            #pragma unroll
            for (int ci = 0; ci < 16; ci++) {
                int mi = half * 16 + ci;
                int m = mw * 32 + mi;
                float4 t = tbl[m];
                float sa = as_a + t.x, sb = as_b + t.x;
                float ca = (sa >= 0.f) ? Esa : Fsa;
                float cb = (sb >= 0.f) ? Esb : Fsb;
                if (!((wa >> mi) & 1u)) ca = 0.f;
                if (!((wb >> mi) & 1u)) cb = 0.f;
                float ea = ca * ((sa >= 0.f) ? t.y : t.z);
                float eb = cb * ((sb >= 0.f) ? t.y : t.z);
                ea16[ci] = ea; eb16[ci] = eb;
                unsigned long long pa = pk2(ea, ea);
                unsigned long long pb = pk2(eb, eb);
                const unsigned long long* hq =
                    (const unsigned long long*)(hp_s + m * 16);
                #pragma unroll
                for (int q = 0; q < 8; q++) {
                    acc[q]     = fma2(pa, hq[q], acc[q]);
                    acc[8 + q] = fma2(pb, hq[q], acc[8 + q]);
                }
            }
            float4* oa = (float4*)(ob + (size_t)na * 512 + mw * 32 + half * 16);
            float4* obp = (float4*)(ob + (size_t)nb * 512 + mw * 32 + half * 16);
            __stcs(oa + 0, make_float4(ea16[0],  ea16[1],  ea16[2],  ea16[3]));
            __stcs(oa + 1, make_float4(ea16[4],  ea16[5],  ea16[6],  ea16[7]));
            __stcs(oa + 2, make_float4(ea16[8],  ea16[9],  ea16[10], ea16[11]));
            __stcs(oa + 3, make_float4(ea16[12], ea16[13], ea16[14], ea16[15]));
            __stcs(obp + 0, make_float4(eb16[0],  eb16[1],  eb16[2],  eb16[3]));
            __stcs(obp + 1, make_float4(eb16[4],  eb16[5],  eb16[6],  eb16[7]));
            __stcs(obp + 2, make_float4(eb16[8],  eb16[9],  eb16[10], eb16[11]));
            __stcs(obp + 3, make_float4(eb16[12], eb16[13], eb16[14], eb16[15]));
        }
    }

    // ---- epilogue: +b1, elu, scatter to g_x ----
    float va[16], vb[16];
    #pragma unroll
    for (int q = 0; q < 8; q++) {
        upk2(acc[q],     va[2 * q], va[2 * q + 1]);
        upk2(acc[8 + q], vb[2 * q], vb[2 * q + 1]);
    }
    float ra[16], rb[16];
    #pragma unroll
    for (int k = 0; k < 16; k++) {
        float xa = va[k] + b1s[k];
        float xb = vb[k] + b1s[k];
        ra[k] = xa > 0.f ? xa : expm1f(xa);
        rb[k] = xb > 0.f ? xb : expm1f(xb);
    }
    float* da = &g_x[(size_t)(b * 512 + na) * 128 + h * 16];
    float* db = &g_x[(size_t)(b * 512 + nb) * 128 + h * 16];
    #pragma unroll
    for (int q = 0; q < 4; q++) {
        ((float4*)da)[q] = make_float4(ra[4*q], ra[4*q+1], ra[4*q+2], ra[4*q+3]);
        ((float4*)db)[q] = make_float4(rb[4*q], rb[4*q+1], rb[4*q+2], rb[4*q+3]);
    }
}

// ---------------- K3: layer-2 projection + attention scalars ----------------
// grid (8, 32), block 256
__global__ void __launch_bounds__(256) k_proj2(
    const int* __restrict__ v_types, const float* __restrict__ w2,
    const float* __restrict__ a_src2, const float* __restrict__ a_dst2)
{
    extern __shared__ float sm4[];
    float* ws  = sm4;          // 24576: already [t][f][o]
    float* asw = ws + 24576;   // 64
    float* adw = asw + 64;     // 64
    float* xv  = adw + 64;     // 512 (4 nodes x 128)
    float* pr  = xv + 512;     // 16
    int tid = threadIdx.x, b = blockIdx.y, bx = blockIdx.x;

    for (int i = tid; i < 24576; i += 256) ws[i] = w2[i];
    if (tid < 64) { asw[tid] = a_src2[tid]; adw[tid] = a_dst2[tid]; }

    int sub = tid >> 6, o = tid & 63, w8 = tid >> 5, lane = tid & 31;
    for (int it = 0; it < 16; it++) {
        int nbase = bx * 64 + it * 4;
        __syncthreads();
        for (int i = tid; i < 512; i += 256)
            xv[i] = g_x[(size_t)(b * 512 + nbase) * 128 + i];
        __syncthreads();
        int n = nbase + sub;
        int ty = v_types[b * 512 + n];
        const float* wp = ws + ty * 8192 + o;
        const float* xp = xv + sub * 128;
        float acc = 0.f;
        #pragma unroll
        for (int f = 0; f < 128; f++) acc = fmaf(xp[f], wp[f * 64], acc);
        g_hp2[(size_t)(b * 512 + n) * 64 + o] = acc;
        float th = tanhf(acc);
        float ps = th * asw[o], pd = th * adw[o];
        #pragma unroll
        for (int off = 16; off; off >>= 1) {
            ps += __shfl_xor_sync(0xffffffffu, ps, off);
            pd += __shfl_xor_sync(0xffffffffu, pd, off);
        }
        if (lane == 0) { pr[w8] = ps; pr[8 + w8] = pd; }
        __syncthreads();
        if (tid < 4) {
            g_as2[b * 512 + nbase + tid] = pr[tid * 2] + pr[tid * 2 + 1];
            g_ad2[b * 512 + nbase + tid] = pr[8 + tid * 2] + pr[8 + tid * 2 + 1];
        }
    }
}

// ---------------- K4: layer-2 rows 0/1 + MLP + log_softmax ----------------
__global__ void __launch_bounds__(512) k_final(
    const float* __restrict__ b2,
    const float* __restrict__ fc1_w, const float* __restrict__ fc1_b,
    const float* __restrict__ fc2_w, const float* __restrict__ fc2_b,
    const float* __restrict__ fc3_w, const float* __restrict__ fc3_b,
    float* __restrict__ out_scores, float* __restrict__ out_vsm)
{
    __shared__ float att2[2 * 512];
    __shared__ float inv[2];
    __shared__ float part[512];
    __shared__ float xrow[128];
    __shared__ float vsm[64], v1[192], v2s[64];
    __shared__ float red[32];
    __shared__ float sc[2];
    int tid = threadIdx.x, b = blockIdx.x;
    int lane = tid & 31, wid = tid >> 5;

    float ad2 = g_ad2[b * 512 + tid];
    unsigned wrd  = g_bits[b * 8192 + (tid >> 5)];
    unsigned wrd1 = g_bits[b * 8192 + 16 + (tid >> 5)];
    float as0 = g_as2[b * 512 + 0], as1 = g_as2[b * 512 + 1];
    float s0 = as0 + ad2, s1 = as1 + ad2;
    float e0 = ((wrd  >> lane) & 1u) ? expf(s0 >= 0.f ? s0 : 0.2f * s0) : 0.f;
    float e1 = ((wrd1 >> lane) & 1u) ? expf(s1 >= 0.f ? s1 : 0.2f * s1) : 0.f;
    att2[tid] = e0;
    att2[512 + tid] = e1;
    float p0 = e0, p1 = e1;
    #pragma unroll
    for (int off = 16; off; off >>= 1) {
        p0 += __shfl_xor_sync(0xffffffffu, p0, off);
        p1 += __shfl_xor_sync(0xffffffffu, p1, off);
    }
    if (lane == 0) { red[wid] = p0; red[16 + wid] = p1; }
    __syncthreads();
    if (tid < 32) {
        float v = red[tid];
        #pragma unroll
        for (int off = 8; off; off >>= 1)
            v += __shfl_xor_sync(0xffffffffu, v, off);
        if (tid == 0)  inv[0] = 1.f / v;
        if (tid == 16) inv[1] = 1.f / v;
    }
    __syncthreads();

    {
        int r = tid >> 8, o = tid & 63, sub = (tid >> 6) & 3;
        const float* hp = g_hp2 + (size_t)b * 32768 + o;
        const float* av = att2 + r * 512 + sub * 128;
        float a0 = 0.f, a1 = 0.f, a2 = 0.f, a3 = 0.f;
        int mb = sub * 128;
        #pragma unroll 4
        for (int k = 0; k < 128; k += 4) {
            a0 = fmaf(av[k],     hp[(size_t)(mb + k) * 64],     a0);
            a1 = fmaf(av[k + 1], hp[(size_t)(mb + k + 1) * 64], a1);
            a2 = fmaf(av[k + 2], hp[(size_t)(mb + k + 2) * 64], a2);
            a3 = fmaf(av[k + 3], hp[(size_t)(mb + k + 3) * 64], a3);
        }
        part[tid] = (a0 + a1) + (a2 + a3);
    }
    __syncthreads();
    if (tid < 128) {
        int r = tid >> 6, o = tid & 63;
        float x = (part[r * 256 + o] + part[r * 256 + 64 + o] +
                   part[r * 256 + 128 + o] + part[r * 256 + 192 + o]) * inv[r] + b2[o];
        xrow[tid] = x > 0.f ? x : expm1f(x);
    }
    __syncthreads();
    if (tid < 64) {
        float vv = xrow[tid] * xrow[64 + tid];
        vsm[tid] = vv;
        out_vsm[b * 64 + tid] = vv;
    }
    __syncthreads();
    if (tid < 192) {
        float acc = fc1_b[tid];
        for (int f = 0; f < 64; f++) acc = fmaf(vsm[f], fc1_w[f * 192 + tid], acc);
        v1[tid] = fmaxf(acc, 0.f);
    }
    __syncthreads();
    if (tid < 64) {
        float acc = fc2_b[tid];
        for (int f = 0; f < 192; f++) acc = fmaf(v1[f], fc2_w[f * 64 + tid], acc);
        v2s[tid] = fmaxf(acc, 0.f);
    }
    __syncthreads();
    if (tid < 2) {
        float acc = fc3_b[tid];
        for (int f = 0; f < 64; f++) acc = fmaf(v2s[f], fc3_w[f * 2 + tid], acc);
        sc[tid] = acc;
    }
    __syncthreads();
    if (tid < 2) {
        float m = fmaxf(sc[0], sc[1]);
        float lse = m + logf(expf(sc[0] - m) + expf(sc[1] - m));
        out_scores[b * 2 + tid] = sc[tid] - lse;
    }
}

// ---------------- launch ----------------
extern "C" void kernel_launch(void* const* d_in, const int* in_sizes, int n_in,
                              void* d_out, int out_size) {
    (void)in_sizes; (void)n_in; (void)out_size;
    const float* features = (const float*)d_in[0];
    const int*   adj      = (const int*)  d_in[1];
    const float* line_emb = (const float*)d_in[5];
    const int*   v_types  = (const int*)  d_in[6];
    const float* w1       = (const float*)d_in[7];
    const float* a_src1   = (const float*)d_in[8];
    const float* a_dst1   = (const float*)d_in[9];
    const float* b1       = (const float*)d_in[10];
    const float* w2       = (const float*)d_in[11];
    const float* a_src2   = (const float*)d_in[12];
    const float* a_dst2   = (const float*)d_in[13];
    const float* b2       = (const float*)d_in[14];
    const float* fc1_w    = (const float*)d_in[15];
    const float* fc1_b    = (const float*)d_in[16];
    const float* fc2_w    = (const float*)d_in[17];
    const float* fc2_b    = (const float*)d_in[18];
    const float* fc3_w    = (const float*)d_in[19];
    const float* fc3_b    = (const float*)d_in[20];

    float* out   = (float*)d_out;
    float* vsm   = out + 64;       // v_sim_mul [32,64]
    float* attn1 = out + 2112;     // attn1 [32,8,512,512]

    cudaFuncSetAttribute(k_proj1, cudaFuncAttributeMaxDynamicSharedMemorySize, 100000);
    cudaFuncSetAttribute(k_fuse,  cudaFuncAttributeMaxDynamicSharedMemorySize, 58000);
    cudaFuncSetAttribute(k_proj2, cudaFuncAttributeMaxDynamicSharedMemorySize, 101000);

    k_pack <<<32768, 256>>>(adj);
    k_proj1<<<dim3(8, 32), 256, 99840>>>(features, line_emb, v_types, w1, a_src1, a_dst1);
    k_fuse <<<dim3(2, 8, 32), 128, 57408>>>(b1, attn1);
    k_proj2<<<dim3(8, 32), 256, 100928>>>(v_types, w2, a_src2, a_dst2);
    k_final<<<32, 512>>>(b2, fc1_w, fc1_b, fc2_w, fc2_b, fc3_w, fc3_b, out, vsm);
}

// round 5
// speedup vs baseline: 1.4451x; 1.0164x over previous
#include <cuda_runtime.h>
#include <cuda_bf16.h>
#include <math.h>

#define NBATCH 32
#define NNODE  512
#define NHEAD  8
#define FHID   16

// ---------------- scratch (device globals; no allocations) ----------------
__device__ float    g_hp1[NBATCH*NHEAD*NNODE*FHID];   // 8 MB
__device__ float    g_as [NBATCH*NHEAD*NNODE];
__device__ float    g_Es [NBATCH*NHEAD*NNODE];
__device__ float    g_Fs [NBATCH*NHEAD*NNODE];
__device__ float    g_ad [NBATCH*NHEAD*NNODE];
__device__ float    g_Ed [NBATCH*NHEAD*NNODE];
__device__ float    g_Fd [NBATCH*NHEAD*NNODE];
__device__ unsigned g_bits[NBATCH*NNODE*16];          // 1 MB bit-packed adjacency
__device__ float    g_x  [NBATCH*NNODE*128];          // 8 MB layer-2 input
__device__ float    g_hp2[NBATCH*NNODE*64];           // 4 MB
__device__ float    g_as2[NBATCH*NNODE];
__device__ float    g_ad2[NBATCH*NNODE];

// ---------------- packed f32x2 helpers (sm_103a) ----------------
static __device__ __forceinline__ unsigned long long pk2(float lo, float hi) {
    unsigned long long r;
    asm("mov.b64 %0,{%1,%2};" : "=l"(r) : "f"(lo), "f"(hi));
    return r;
}
static __device__ __forceinline__ void upk2(unsigned long long v, float& lo, float& hi) {
    asm("mov.b64 {%0,%1},%2;" : "=f"(lo), "=f"(hi) : "l"(v));
}
static __device__ __forceinline__ unsigned long long fma2(unsigned long long a,
                                                          unsigned long long b,
                                                          unsigned long long c) {
    unsigned long long d;
    asm("fma.rn.f32x2 %0,%1,%2,%3;" : "=l"(d) : "l"(a), "l"(b), "l"(c));
    return d;
}

// ---------------- K0: bit-pack adjacency ----------------
__global__ void k_pack(const int* __restrict__ adj) {
    int idx = blockIdx.x * 256 + threadIdx.x;
    unsigned m = __ballot_sync(0xffffffffu, adj[idx] > 0);
    if ((threadIdx.x & 31) == 0) g_bits[idx >> 5] = m;
}

// ---------------- K1: layer-1 projection + tanh + exp tables ----------------
// grid (8, 2, 32) = (node-tile, head-half, batch), block 256
// smem: ws 12288 + emb 4096 + asr 64 + ads 64 + vt 64 -> 66304 B (2 blocks/SM)
__global__ void __launch_bounds__(256) k_proj1(
    const float* __restrict__ features, const float* __restrict__ line_emb,
    const int*   __restrict__ v_types,  const float* __restrict__ w1,
    const float* __restrict__ a_src1,   const float* __restrict__ a_dst1)
{
    extern __shared__ float sm1[];
    float* ws   = sm1;             // 12288: [t][f][l64]  (l64 = hloc*16+o)
    float* embs = ws + 12288;      // 4096: 64 nodes x 64
    float* asr  = embs + 4096;     // 64
    float* ads  = asr + 64;        // 64
    int*   vt   = (int*)(ads + 64);// 64
    int tid = threadIdx.x;
    int bx = blockIdx.x, hh = blockIdx.y, b = blockIdx.z;
    int nbase = bx * 64;

    for (int i = tid; i < 12288; i += 256) {
        int l64 = i & 63, f = (i >> 6) & 63, t = i >> 12;
        int h = hh * 4 + (l64 >> 4), o = l64 & 15;
        ws[i] = w1[((t * 8 + h) * 64 + f) * 16 + o];
    }
    for (int i = tid; i < 4096; i += 256) {
        int node = i >> 6, f = i & 63;
        int n = nbase + node;
        embs[i] = (f < 32) ? features[(b * NNODE + n) * 32 + f]
                           : line_emb[(b * NNODE + n) * 32 + f - 32];
    }
    if (tid < 64) {
        int h = hh * 4 + (tid >> 4), o = tid & 15;
        asr[tid] = a_src1[h * 16 + o];
        ads[tid] = a_dst1[h * 16 + o];
        vt[tid] = v_types[b * NNODE + nbase + tid];
    }
    __syncthreads();

    int sub = tid >> 6, l64 = tid & 63;
    int h = hh * 4 + (l64 >> 4), o = l64 & 15;
    float av = asr[l64], dv = ads[l64];
    for (int it = 0; it < 16; it++) {
        int nloc = it * 4 + sub;
        int n = nbase + nloc;
        int ty = vt[nloc];
        const float* wr = ws + ty * 4096 + l64;
        const float* ev = embs + nloc * 64;
        float a0 = 0.f, a1 = 0.f, a2 = 0.f, a3 = 0.f;
        #pragma unroll
        for (int j = 0; j < 16; j++) {
            a0 = fmaf(ev[4 * j + 0], wr[(4 * j + 0) * 64], a0);
            a1 = fmaf(ev[4 * j + 1], wr[(4 * j + 1) * 64], a1);
            a2 = fmaf(ev[4 * j + 2], wr[(4 * j + 2) * 64], a2);
            a3 = fmaf(ev[4 * j + 3], wr[(4 * j + 3) * 64], a3);
        }
        float acc = (a0 + a1) + (a2 + a3);
        g_hp1[((b * NHEAD + h) * NNODE + n) * FHID + o] = acc;
        float th = tanhf(acc);
        float ps = th * av, pd = th * dv;
        #pragma unroll
        for (int off = 8; off; off >>= 1) {
            ps += __shfl_xor_sync(0xffffffffu, ps, off);
            pd += __shfl_xor_sync(0xffffffffu, pd, off);
        }
        if (o == 0) {
            int ai = (b * NHEAD + h) * NNODE + n;
            g_as[ai] = ps; g_Es[ai] = expf(ps); g_Fs[ai] = expf(0.2f * ps);
            g_ad[ai] = pd; g_Ed[ai] = expf(pd); g_Fd[ai] = expf(0.2f * pd);
        }
    }
}

// ---------------- K2: FUSED attn softmax + attn1 store + out1 GEMM + elu ----------------
// grid (2, 8, 32) = (nhalf, h, b), 128 threads, dyn smem 57408 B
__global__ void __launch_bounds__(128) k_fuse(const float* __restrict__ b1,
                                              float* __restrict__ attn_out) {
    extern __shared__ float smf[];
    float*    hp_s   = smf;                       // 8192 floats [m][o]
    float4*   tbl    = (float4*)(smf + 8192);     // 512 float4 (ad, Ed, Fd, 0)
    unsigned* bits_s = (unsigned*)(smf + 10240);  // 4096 words, layout [w][r]
    float*    b1s    = smf + 14336;               // 16
    int tid = threadIdx.x;
    int nh = blockIdx.x, h = blockIdx.y, b = blockIdx.z;
    int bh = b * NHEAD + h;
    int n0 = nh * 256;

    for (int i = tid; i < 8192; i += 128) hp_s[i] = g_hp1[bh * 8192 + i];
    for (int i = tid; i < 512; i += 128)
        tbl[i] = make_float4(g_ad[bh * 512 + i], g_Ed[bh * 512 + i],
                             g_Fd[bh * 512 + i], 0.f);
    for (int i = tid; i < 4096; i += 128) {
        int w = i >> 8, r = i & 255;
        bits_s[i] = g_bits[b * 8192 + (n0 + r) * 16 + w];
    }
    if (tid < 16) b1s[tid] = b1[tid];

    int rla = tid * 2, rlb = rla + 1;
    int na = n0 + rla, nb = n0 + rlb;
    float as_a = g_as[bh * 512 + na], as_b = g_as[bh * 512 + nb];
    float Es_a = g_Es[bh * 512 + na], Fs_a = g_Fs[bh * 512 + na];
    float Es_b = g_Es[bh * 512 + nb], Fs_b = g_Fs[bh * 512 + nb];
    __syncthreads();

    // pass A: row sums
    float SEa = 0.f, SFa = 0.f, SEb = 0.f, SFb = 0.f;
    for (int mw = 0; mw < 16; mw++) {
        unsigned wa = bits_s[mw * 256 + rla];
        unsigned wb = bits_s[mw * 256 + rlb];
        #pragma unroll
        for (int mi = 0; mi < 32; mi++) {
            float4 t = tbl[mw * 32 + mi];
            float sa = as_a + t.x, sb = as_b + t.x;
            bool ba = (wa >> mi) & 1u, bb = (wb >> mi) & 1u;
            SEa += (ba && sa >= 0.f) ? t.y : 0.f;
            SFa += (ba && sa <  0.f) ? t.z : 0.f;
            SEb += (bb && sb >= 0.f) ? t.y : 0.f;
            SFb += (bb && sb <  0.f) ? t.z : 0.f;
        }
    }
    float inva = 1.f / fmaf(Es_a, SEa, Fs_a * SFa);
    float invb = 1.f / fmaf(Es_b, SEb, Fs_b * SFb);
    float Esa = Es_a * inva, Fsa = Fs_a * inva;
    float Esb = Es_b * invb, Fsb = Fs_b * invb;

    // pass B: attn recompute + store + fma2 GEMM
    unsigned long long acc[16];
    unsigned long long z = pk2(0.f, 0.f);
    #pragma unroll
    for (int q = 0; q < 16; q++) acc[q] = z;

    float* ob = attn_out + (size_t)bh * 512 * 512;
    for (int mw = 0; mw < 16; mw++) {
        unsigned wa = bits_s[mw * 256 + rla];
        unsigned wb = bits_s[mw * 256 + rlb];
        #pragma unroll
        for (int half = 0; half < 2; half++) {
            float ea16[16], eb16[16];
            #pragma unroll
            for (int ci = 0; ci < 16; ci++) {
                int mi = half * 16 + ci;
                int m = mw * 32 + mi;
                float4 t = tbl[m];
                float sa = as_a + t.x, sb = as_b + t.x;
                float ca = (sa >= 0.f) ? Esa : Fsa;
                float cb = (sb >= 0.f) ? Esb : Fsb;
                if (!((wa >> mi) & 1u)) ca = 0.f;
                if (!((wb >> mi) & 1u)) cb = 0.f;
                float ea = ca * ((sa >= 0.f) ? t.y : t.z);
                float eb = cb * ((sb >= 0.f) ? t.y : t.z);
                ea16[ci] = ea; eb16[ci] = eb;
                unsigned long long pa = pk2(ea, ea);
                unsigned long long pb = pk2(eb, eb);
                const unsigned long long* hq =
                    (const unsigned long long*)(hp_s + m * 16);
                #pragma unroll
                for (int q = 0; q < 8; q++) {
                    acc[q]     = fma2(pa, hq[q], acc[q]);
                    acc[8 + q] = fma2(pb, hq[q], acc[8 + q]);
                }
            }
            float4* oa  = (float4*)(ob + (size_t)na * 512 + mw * 32 + half * 16);
            float4* obp = (float4*)(ob + (size_t)nb * 512 + mw * 32 + half * 16);
            __stcs(oa + 0, make_float4(ea16[0],  ea16[1],  ea16[2],  ea16[3]));
            __stcs(oa + 1, make_float4(ea16[4],  ea16[5],  ea16[6],  ea16[7]));
            __stcs(oa + 2, make_float4(ea16[8],  ea16[9],  ea16[10], ea16[11]));
            __stcs(oa + 3, make_float4(ea16[12], ea16[13], ea16[14], ea16[15]));
            __stcs(obp + 0, make_float4(eb16[0],  eb16[1],  eb16[2],  eb16[3]));
            __stcs(obp + 1, make_float4(eb16[4],  eb16[5],  eb16[6],  eb16[7]));
            __stcs(obp + 2, make_float4(eb16[8],  eb16[9],  eb16[10], eb16[11]));
            __stcs(obp + 3, make_float4(eb16[12], eb16[13], eb16[14], eb16[15]));
        }
    }

    // epilogue
    float va[16], vb[16];
    #pragma unroll
    for (int q = 0; q < 8; q++) {
        upk2(acc[q],     va[2 * q], va[2 * q + 1]);
        upk2(acc[8 + q], vb[2 * q], vb[2 * q + 1]);
    }
    float ra[16], rb[16];
    #pragma unroll
    for (int k = 0; k < 16; k++) {
        float xa = va[k] + b1s[k];
        float xb = vb[k] + b1s[k];
        ra[k] = xa > 0.f ? xa : expm1f(xa);
        rb[k] = xb > 0.f ? xb : expm1f(xb);
    }
    float* da = &g_x[(size_t)(b * 512 + na) * 128 + h * 16];
    float* db = &g_x[(size_t)(b * 512 + nb) * 128 + h * 16];
    #pragma unroll
    for (int q = 0; q < 4; q++) {
        ((float4*)da)[q] = make_float4(ra[4*q], ra[4*q+1], ra[4*q+2], ra[4*q+3]);
        ((float4*)db)[q] = make_float4(rb[4*q], rb[4*q+1], rb[4*q+2], rb[4*q+3]);
    }
}

// ---------------- K3: layer-2 projection + attention scalars ----------------
// grid (8, 32), block 512
// smem: ws 24576 + xv 8192 + asw 64 + adw 64 + vt 64 + pr 256 -> 133 KB (1 blk/SM)
__global__ void __launch_bounds__(512) k_proj2(
    const int* __restrict__ v_types, const float* __restrict__ w2,
    const float* __restrict__ a_src2, const float* __restrict__ a_dst2)
{
    extern __shared__ float sm4[];
    float* ws  = sm4;            // 24576: [t][f][o]
    float* xv  = ws + 24576;     // 8192: 64 nodes x 128
    float* asw = xv + 8192;      // 64
    float* adw = asw + 64;       // 64
    int*   vt  = (int*)(adw + 64); // 64
    float* prs = (float*)(vt + 64);  // 128 (ps per warp per iter)
    float* prd = prs + 128;          // 128
    int tid = threadIdx.x, b = blockIdx.y, bx = blockIdx.x;
    int nbase = bx * 64;

    for (int i = tid; i < 24576; i += 512) ws[i] = w2[i];
    for (int i = tid; i < 8192; i += 512)
        xv[i] = g_x[(size_t)(b * 512 + nbase) * 128 + i];
    if (tid < 64) {
        asw[tid] = a_src2[tid];
        adw[tid] = a_dst2[tid];
        vt[tid] = v_types[b * 512 + nbase + tid];
    }
    __syncthreads();

    int sub = tid >> 6, o = tid & 63, w = tid >> 5, lane = tid & 31;
    float av = asw[o], dv = adw[o];
    for (int it = 0; it < 8; it++) {
        int nloc = it * 8 + sub;
        int ty = vt[nloc];
        const float* wp = ws + ty * 8192 + o;
        const float* xp = xv + nloc * 128;
        float a0 = 0.f, a1 = 0.f, a2 = 0.f, a3 = 0.f;
        #pragma unroll
        for (int j = 0; j < 32; j++) {
            a0 = fmaf(xp[4 * j + 0], wp[(4 * j + 0) * 64], a0);
            a1 = fmaf(xp[4 * j + 1], wp[(4 * j + 1) * 64], a1);
            a2 = fmaf(xp[4 * j + 2], wp[(4 * j + 2) * 64], a2);
            a3 = fmaf(xp[4 * j + 3], wp[(4 * j + 3) * 64], a3);
        }
        float acc = (a0 + a1) + (a2 + a3);
        g_hp2[(size_t)(b * 512 + nbase + nloc) * 64 + o] = acc;
        float th = tanhf(acc);
        float ps = th * av, pd = th * dv;
        #pragma unroll
        for (int off = 16; off; off >>= 1) {
            ps += __shfl_xor_sync(0xffffffffu, ps, off);
            pd += __shfl_xor_sync(0xffffffffu, pd, off);
        }
        if (lane == 0) { prs[it * 16 + w] = ps; prd[it * 16 + w] = pd; }
    }
    __syncthreads();
    if (tid < 64) {
        int idx = (tid >> 3) * 16 + (tid & 7) * 2;
        g_as2[b * 512 + nbase + tid] = prs[idx] + prs[idx + 1];
        g_ad2[b * 512 + nbase + tid] = prd[idx] + prd[idx + 1];
    }
}

// ---------------- K4: layer-2 rows 0/1 + MLP + log_softmax ----------------
__global__ void __launch_bounds__(512) k_final(
    const float* __restrict__ b2,
    const float* __restrict__ fc1_w, const float* __restrict__ fc1_b,
    const float* __restrict__ fc2_w, const float* __restrict__ fc2_b,
    const float* __restrict__ fc3_w, const float* __restrict__ fc3_b,
    float* __restrict__ out_scores, float* __restrict__ out_vsm)
{
    __shared__ float att2[2 * 512];
    __shared__ float inv[2];
    __shared__ float part[512];
    __shared__ float xrow[128];
    __shared__ float vsm[64], v1[192], v2s[64];
    __shared__ float red[32];
    __shared__ float sc[2];
    int tid = threadIdx.x, b = blockIdx.x;
    int lane = tid & 31, wid = tid >> 5;

    float ad2 = g_ad2[b * 512 + tid];
    unsigned wrd  = g_bits[b * 8192 + (tid >> 5)];
    unsigned wrd1 = g_bits[b * 8192 + 16 + (tid >> 5)];
    float as0 = g_as2[b * 512 + 0], as1 = g_as2[b * 512 + 1];
    float s0 = as0 + ad2, s1 = as1 + ad2;
    float e0 = ((wrd  >> lane) & 1u) ? expf(s0 >= 0.f ? s0 : 0.2f * s0) : 0.f;
    float e1 = ((wrd1 >> lane) & 1u) ? expf(s1 >= 0.f ? s1 : 0.2f * s1) : 0.f;
    att2[tid] = e0;
    att2[512 + tid] = e1;
    float p0 = e0, p1 = e1;
    #pragma unroll
    for (int off = 16; off; off >>= 1) {
        p0 += __shfl_xor_sync(0xffffffffu, p0, off);
        p1 += __shfl_xor_sync(0xffffffffu, p1, off);
    }
    if (lane == 0) { red[wid] = p0; red[16 + wid] = p1; }
    __syncthreads();
    if (tid < 32) {
        float v = red[tid];
        #pragma unroll
        for (int off = 8; off; off >>= 1)
            v += __shfl_xor_sync(0xffffffffu, v, off);
        if (tid == 0)  inv[0] = 1.f / v;
        if (tid == 16) inv[1] = 1.f / v;
    }
    __syncthreads();

    {
        int r = tid >> 8, o = tid & 63, sub = (tid >> 6) & 3;
        const float* hp = g_hp2 + (size_t)b * 32768 + o;
        const float* av = att2 + r * 512 + sub * 128;
        float a0 = 0.f, a1 = 0.f, a2 = 0.f, a3 = 0.f;
        int mb = sub * 128;
        #pragma unroll 4
        for (int k = 0; k < 128; k += 4) {
            a0 = fmaf(av[k],     hp[(size_t)(mb + k) * 64],     a0);
            a1 = fmaf(av[k + 1], hp[(size_t)(mb + k + 1) * 64], a1);
            a2 = fmaf(av[k + 2], hp[(size_t)(mb + k + 2) * 64], a2);
            a3 = fmaf(av[k + 3], hp[(size_t)(mb + k + 3) * 64], a3);
        }
        part[tid] = (a0 + a1) + (a2 + a3);
    }
    __syncthreads();
    if (tid < 128) {
        int r = tid >> 6, o = tid & 63;
        float x = (part[r * 256 + o] + part[r * 256 + 64 + o] +
                   part[r * 256 + 128 + o] + part[r * 256 + 192 + o]) * inv[r] + b2[o];
        xrow[tid] = x > 0.f ? x : expm1f(x);
    }
    __syncthreads();
    if (tid < 64) {
        float vv = xrow[tid] * xrow[64 + tid];
        vsm[tid] = vv;
        out_vsm[b * 64 + tid] = vv;
    }
    __syncthreads();
    if (tid < 192) {
        float acc = fc1_b[tid];
        for (int f = 0; f < 64; f++) acc = fmaf(vsm[f], fc1_w[f * 192 + tid], acc);
        v1[tid] = fmaxf(acc, 0.f);
    }
    __syncthreads();
    if (tid < 64) {
        float acc = fc2_b[tid];
        for (int f = 0; f < 192; f++) acc = fmaf(v1[f], fc2_w[f * 64 + tid], acc);
        v2s[tid] = fmaxf(acc, 0.f);
    }
    __syncthreads();
    if (tid < 2) {
        float acc = fc3_b[tid];
        for (int f = 0; f < 64; f++) acc = fmaf(v2s[f], fc3_w[f * 2 + tid], acc);
        sc[tid] = acc;
    }
    __syncthreads();
    if (tid < 2) {
        float m = fmaxf(sc[0], sc[1]);
        float lse = m + logf(expf(sc[0] - m) + expf(sc[1] - m));
        out_scores[b * 2 + tid] = sc[tid] - lse;
    }
}

// ---------------- launch ----------------
extern "C" void kernel_launch(void* const* d_in, const int* in_sizes, int n_in,
                              void* d_out, int out_size) {
    (void)in_sizes; (void)n_in; (void)out_size;
    const float* features = (const float*)d_in[0];
    const int*   adj      = (const int*)  d_in[1];
    const float* line_emb = (const float*)d_in[5];
    const int*   v_types  = (const int*)  d_in[6];
    const float* w1       = (const float*)d_in[7];
    const float* a_src1   = (const float*)d_in[8];
    const float* a_dst1   = (const float*)d_in[9];
    const float* b1       = (const float*)d_in[10];
    const float* w2       = (const float*)d_in[11];
    const float* a_src2   = (const float*)d_in[12];
    const float* a_dst2   = (const float*)d_in[13];
    const float* b2       = (const float*)d_in[14];
    const float* fc1_w    = (const float*)d_in[15];
    const float* fc1_b    = (const float*)d_in[16];
    const float* fc2_w    = (const float*)d_in[17];
    const float* fc2_b    = (const float*)d_in[18];
    const float* fc3_w    = (const float*)d_in[19];
    const float* fc3_b    = (const float*)d_in[20];

    float* out   = (float*)d_out;
    float* vsm   = out + 64;       // v_sim_mul [32,64]
    float* attn1 = out + 2112;     // attn1 [32,8,512,512]

    cudaFuncSetAttribute(k_proj1, cudaFuncAttributeMaxDynamicSharedMemorySize, 67000);
    cudaFuncSetAttribute(k_fuse,  cudaFuncAttributeMaxDynamicSharedMemorySize, 58000);
    cudaFuncSetAttribute(k_proj2, cudaFuncAttributeMaxDynamicSharedMemorySize, 135000);

    k_pack <<<32768, 256>>>(adj);
    k_proj1<<<dim3(8, 2, 32), 256, 66304>>>(features, line_emb, v_types, w1, a_src1, a_dst1);
    k_fuse <<<dim3(2, 8, 32), 128, 57408>>>(b1, attn1);
    k_proj2<<<dim3(8, 32), 512, 134400>>>(v_types, w2, a_src2, a_dst2);
    k_final<<<32, 512>>>(b2, fc1_w, fc1_b, fc2_w, fc2_b, fc3_w, fc3_b, out, vsm);
}

// round 6
// speedup vs baseline: 1.5700x; 1.0864x over previous
#include <cuda_runtime.h>
#include <cuda_bf16.h>
#include <math.h>

#define NBATCH 32
#define NNODE  512
#define NHEAD  8
#define FHID   16

// ---------------- scratch (device globals; no allocations) ----------------
__device__ float    g_hp1[NBATCH*NHEAD*NNODE*FHID];   // 8 MB
__device__ float    g_as [NBATCH*NHEAD*NNODE];
__device__ float    g_Es [NBATCH*NHEAD*NNODE];
__device__ float    g_Fs [NBATCH*NHEAD*NNODE];
__device__ float    g_ad [NBATCH*NHEAD*NNODE];
__device__ float    g_Ed [NBATCH*NHEAD*NNODE];
__device__ float    g_Fd [NBATCH*NHEAD*NNODE];
__device__ unsigned g_bits[NBATCH*NNODE*16];          // 1 MB bit-packed adjacency
__device__ float    g_x  [NBATCH*NNODE*128];          // 8 MB layer-2 input
__device__ float    g_hp2[NBATCH*NNODE*64];           // 4 MB
__device__ float    g_as2[NBATCH*NNODE];
__device__ float    g_ad2[NBATCH*NNODE];

// ---------------- packed f32x2 helpers (sm_103a) ----------------
static __device__ __forceinline__ unsigned long long pk2(float lo, float hi) {
    unsigned long long r;
    asm("mov.b64 %0,{%1,%2};" : "=l"(r) : "f"(lo), "f"(hi));
    return r;
}
static __device__ __forceinline__ void upk2(unsigned long long v, float& lo, float& hi) {
    asm("mov.b64 {%0,%1},%2;" : "=f"(lo), "=f"(hi) : "l"(v));
}
static __device__ __forceinline__ unsigned long long fma2(unsigned long long a,
                                                          unsigned long long b,
                                                          unsigned long long c) {
    unsigned long long d;
    asm("fma.rn.f32x2 %0,%1,%2,%3;" : "=l"(d) : "l"(a), "l"(b), "l"(c));
    return d;
}
static __device__ __forceinline__ unsigned long long add2(unsigned long long a,
                                                          unsigned long long b) {
    unsigned long long d;
    asm("add.rn.f32x2 %0,%1,%2;" : "=l"(d) : "l"(a), "l"(b));
    return d;
}

// ---------------- K0: bit-pack adjacency ----------------
__global__ void k_pack(const int* __restrict__ adj) {
    int idx = blockIdx.x * 256 + threadIdx.x;
    unsigned m = __ballot_sync(0xffffffffu, adj[idx] > 0);
    if ((threadIdx.x & 31) == 0) g_bits[idx >> 5] = m;
}

// ---------------- K1: layer-1 projection + tanh + exp tables ----------------
// grid (8, 2, 32) = (node-tile, head-half, batch), block 512
// warp-per-node: lane owns an output PAIR (2 outputs of the 64 = 4 heads x 16)
// smem: ws 12288f + xv 4096f + asr/ads 64f + vt 64i = 66304 B
__global__ void __launch_bounds__(512) k_proj1(
    const float* __restrict__ features, const float* __restrict__ line_emb,
    const int*   __restrict__ v_types,  const float* __restrict__ w1,
    const float* __restrict__ a_src1,   const float* __restrict__ a_dst1)
{
    extern __shared__ float sm1[];
    float* ws   = sm1;             // 12288: [t][f][l64]
    float* xv   = ws + 12288;      // 4096: 64 nodes x 64
    float* asr  = xv + 4096;       // 64
    float* ads  = asr + 64;        // 64
    int*   vt   = (int*)(ads + 64);// 64
    int tid = threadIdx.x;
    int bx = blockIdx.x, hh = blockIdx.y, b = blockIdx.z;
    int nbase = bx * 64;

    for (int i = tid; i < 12288; i += 512) {
        int l64 = i & 63, f = (i >> 6) & 63, t = i >> 12;
        int h = hh * 4 + (l64 >> 4), o = l64 & 15;
        ws[i] = w1[((t * 8 + h) * 64 + f) * 16 + o];
    }
    for (int i = tid; i < 4096; i += 512) {
        int node = i >> 6, f = i & 63;
        int n = nbase + node;
        xv[i] = (f < 32) ? features[(b * NNODE + n) * 32 + f]
                         : line_emb[(b * NNODE + n) * 32 + f - 32];
    }
    if (tid < 64) {
        int h = hh * 4 + (tid >> 4), o = tid & 15;
        asr[tid] = a_src1[h * 16 + o];
        ads[tid] = a_dst1[h * 16 + o];
        vt[tid] = v_types[b * NNODE + nbase + tid];
    }
    __syncthreads();

    int lane = tid & 31, w = tid >> 5;
    int gh = hh * 4 + (lane >> 3);              // global head for this lane
    float a0v = asr[2 * lane], a1v = asr[2 * lane + 1];
    float d0v = ads[2 * lane], d1v = ads[2 * lane + 1];
    unsigned long long z = pk2(0.f, 0.f);

    #pragma unroll
    for (int r = 0; r < 4; r++) {
        int nloc = w * 4 + r;
        int n = nbase + nloc;
        int ty = vt[nloc];
        const float* wp = ws + ty * 4096 + 2 * lane;
        const float* xp = xv + nloc * 64;
        unsigned long long acc0 = z, acc1 = z;
        #pragma unroll
        for (int f = 0; f < 64; f += 2) {
            float2 x2 = *(const float2*)&xp[f];
            unsigned long long w0 = *(const unsigned long long*)&wp[f * 64];
            unsigned long long w1v = *(const unsigned long long*)&wp[(f + 1) * 64];
            acc0 = fma2(pk2(x2.x, x2.x), w0, acc0);
            acc1 = fma2(pk2(x2.y, x2.y), w1v, acc1);
        }
        float v0, v1;
        upk2(add2(acc0, acc1), v0, v1);
        int o = (2 * lane) & 15;
        *(float2*)&g_hp1[((b * NHEAD + gh) * NNODE + n) * FHID + o] =
            make_float2(v0, v1);
        float th0 = tanhf(v0), th1 = tanhf(v1);
        float ps = th0 * a0v + th1 * a1v;
        float pd = th0 * d0v + th1 * d1v;
        #pragma unroll
        for (int off = 4; off; off >>= 1) {
            ps += __shfl_xor_sync(0xffffffffu, ps, off);
            pd += __shfl_xor_sync(0xffffffffu, pd, off);
        }
        if ((lane & 7) == 0) {
            int ai = (b * NHEAD + gh) * NNODE + n;
            g_as[ai] = ps; g_Es[ai] = expf(ps); g_Fs[ai] = expf(0.2f * ps);
            g_ad[ai] = pd; g_Ed[ai] = expf(pd); g_Fd[ai] = expf(0.2f * pd);
        }
    }
}

// ---------------- K2: FUSED attn softmax + attn1 store + out1 GEMM + elu ----------------
// grid (2, 8, 32) = (nhalf, h, b), 128 threads, dyn smem 57408 B
__global__ void __launch_bounds__(128) k_fuse(const float* __restrict__ b1,
                                              float* __restrict__ attn_out) {
    extern __shared__ float smf[];
    float*    hp_s   = smf;                       // 8192 floats [m][o]
    float4*   tbl    = (float4*)(smf + 8192);     // 512 float4 (ad, Ed, Fd, 0)
    unsigned* bits_s = (unsigned*)(smf + 10240);  // 4096 words, layout [w][r]
    float*    b1s    = smf + 14336;               // 16
    int tid = threadIdx.x;
    int nh = blockIdx.x, h = blockIdx.y, b = blockIdx.z;
    int bh = b * NHEAD + h;
    int n0 = nh * 256;

    for (int i = tid; i < 8192; i += 128) hp_s[i] = g_hp1[bh * 8192 + i];
    for (int i = tid; i < 512; i += 128)
        tbl[i] = make_float4(g_ad[bh * 512 + i], g_Ed[bh * 512 + i],
                             g_Fd[bh * 512 + i], 0.f);
    for (int i = tid; i < 4096; i += 128) {
        int w = i >> 8, r = i & 255;
        bits_s[i] = g_bits[b * 8192 + (n0 + r) * 16 + w];
    }
    if (tid < 16) b1s[tid] = b1[tid];

    int rla = tid * 2, rlb = rla + 1;
    int na = n0 + rla, nb = n0 + rlb;
    float as_a = g_as[bh * 512 + na], as_b = g_as[bh * 512 + nb];
    float Es_a = g_Es[bh * 512 + na], Fs_a = g_Fs[bh * 512 + na];
    float Es_b = g_Es[bh * 512 + nb], Fs_b = g_Fs[bh * 512 + nb];
    __syncthreads();

    // pass A: row sums
    float SEa = 0.f, SFa = 0.f, SEb = 0.f, SFb = 0.f;
    for (int mw = 0; mw < 16; mw++) {
        unsigned wa = bits_s[mw * 256 + rla];
        unsigned wb = bits_s[mw * 256 + rlb];
        #pragma unroll
        for (int mi = 0; mi < 32; mi++) {
            float4 t = tbl[mw * 32 + mi];
            float sa = as_a + t.x, sb = as_b + t.x;
            bool ba = (wa >> mi) & 1u, bb = (wb >> mi) & 1u;
            SEa += (ba && sa >= 0.f) ? t.y : 0.f;
            SFa += (ba && sa <  0.f) ? t.z : 0.f;
            SEb += (bb && sb >= 0.f) ? t.y : 0.f;
            SFb += (bb && sb <  0.f) ? t.z : 0.f;
        }
    }
    float inva = 1.f / fmaf(Es_a, SEa, Fs_a * SFa);
    float invb = 1.f / fmaf(Es_b, SEb, Fs_b * SFb);
    float Esa = Es_a * inva, Fsa = Fs_a * inva;
    float Esb = Es_b * invb, Fsb = Fs_b * invb;

    // pass B: attn recompute + store + fma2 GEMM
    unsigned long long acc[16];
    unsigned long long z = pk2(0.f, 0.f);
    #pragma unroll
    for (int q = 0; q < 16; q++) acc[q] = z;

    float* ob = attn_out + (size_t)bh * 512 * 512;
    for (int mw = 0; mw < 16; mw++) {
        unsigned wa = bits_s[mw * 256 + rla];
        unsigned wb = bits_s[mw * 256 + rlb];
        #pragma unroll
        for (int half = 0; half < 2; half++) {
            float ea16[16], eb16[16];
            #pragma unroll
            for (int ci = 0; ci < 16; ci++) {
                int mi = half * 16 + ci;
                int m = mw * 32 + mi;
                float4 t = tbl[m];
                float sa = as_a + t.x, sb = as_b + t.x;
                float ca = (sa >= 0.f) ? Esa : Fsa;
                float cb = (sb >= 0.f) ? Esb : Fsb;
                if (!((wa >> mi) & 1u)) ca = 0.f;
                if (!((wb >> mi) & 1u)) cb = 0.f;
                float ea = ca * ((sa >= 0.f) ? t.y : t.z);
                float eb = cb * ((sb >= 0.f) ? t.y : t.z);
                ea16[ci] = ea; eb16[ci] = eb;
                unsigned long long pa = pk2(ea, ea);
                unsigned long long pb = pk2(eb, eb);
                const unsigned long long* hq =
                    (const unsigned long long*)(hp_s + m * 16);
                #pragma unroll
                for (int q = 0; q < 8; q++) {
                    acc[q]     = fma2(pa, hq[q], acc[q]);
                    acc[8 + q] = fma2(pb, hq[q], acc[8 + q]);
                }
            }
            float4* oa  = (float4*)(ob + (size_t)na * 512 + mw * 32 + half * 16);
            float4* obp = (float4*)(ob + (size_t)nb * 512 + mw * 32 + half * 16);
            __stcs(oa + 0, make_float4(ea16[0],  ea16[1],  ea16[2],  ea16[3]));
            __stcs(oa + 1, make_float4(ea16[4],  ea16[5],  ea16[6],  ea16[7]));
            __stcs(oa + 2, make_float4(ea16[8],  ea16[9],  ea16[10], ea16[11]));
            __stcs(oa + 3, make_float4(ea16[12], ea16[13], ea16[14], ea16[15]));
            __stcs(obp + 0, make_float4(eb16[0],  eb16[1],  eb16[2],  eb16[3]));
            __stcs(obp + 1, make_float4(eb16[4],  eb16[5],  eb16[6],  eb16[7]));
            __stcs(obp + 2, make_float4(eb16[8],  eb16[9],  eb16[10], eb16[11]));
            __stcs(obp + 3, make_float4(eb16[12], eb16[13], eb16[14], eb16[15]));
        }
    }

    // epilogue
    float va[16], vb[16];
    #pragma unroll
    for (int q = 0; q < 8; q++) {
        upk2(acc[q],     va[2 * q], va[2 * q + 1]);
        upk2(acc[8 + q], vb[2 * q], vb[2 * q + 1]);
    }
    float ra[16], rb[16];
    #pragma unroll
    for (int k = 0; k < 16; k++) {
        float xa = va[k] + b1s[k];
        float xb = vb[k] + b1s[k];
        ra[k] = xa > 0.f ? xa : expm1f(xa);
        rb[k] = xb > 0.f ? xb : expm1f(xb);
    }
    float* da = &g_x[(size_t)(b * 512 + na) * 128 + h * 16];
    float* db = &g_x[(size_t)(b * 512 + nb) * 128 + h * 16];
    #pragma unroll
    for (int q = 0; q < 4; q++) {
        ((float4*)da)[q] = make_float4(ra[4*q], ra[4*q+1], ra[4*q+2], ra[4*q+3]);
        ((float4*)db)[q] = make_float4(rb[4*q], rb[4*q+1], rb[4*q+2], rb[4*q+3]);
    }
}

// ---------------- K3: layer-2 projection + attention scalars ----------------
// grid (8, 32), block 512; warp-per-node, lane owns output pair
// smem: ws 24576f + xv 8192f + asw/adw 64f + vt 64i = 131840 B
__global__ void __launch_bounds__(512) k_proj2(
    const int* __restrict__ v_types, const float* __restrict__ w2,
    const float* __restrict__ a_src2, const float* __restrict__ a_dst2)
{
    extern __shared__ float sm4[];
    float* ws  = sm4;              // 24576: [t][f][o]
    float* xv  = ws + 24576;       // 8192: 64 nodes x 128
    float* asw = xv + 8192;        // 64
    float* adw = asw + 64;         // 64
    int*   vt  = (int*)(adw + 64); // 64
    int tid = threadIdx.x, b = blockIdx.y, bx = blockIdx.x;
    int nbase = bx * 64;

    for (int i = tid; i < 24576; i += 512) ws[i] = w2[i];
    for (int i = tid; i < 8192; i += 512)
        xv[i] = g_x[(size_t)(b * 512 + nbase) * 128 + i];
    if (tid < 64) {
        asw[tid] = a_src2[tid];
        adw[tid] = a_dst2[tid];
        vt[tid] = v_types[b * 512 + nbase + tid];
    }
    __syncthreads();

    int lane = tid & 31, w = tid >> 5;
    float a0v = asw[2 * lane], a1v = asw[2 * lane + 1];
    float d0v = adw[2 * lane], d1v = adw[2 * lane + 1];
    unsigned long long z = pk2(0.f, 0.f);

    #pragma unroll
    for (int r = 0; r < 4; r++) {
        int nloc = w * 4 + r;
        int n = nbase + nloc;
        int ty = vt[nloc];
        const float* wp = ws + ty * 8192 + 2 * lane;
        const float* xp = xv + nloc * 128;
        unsigned long long acc0 = z, acc1 = z;
        #pragma unroll
        for (int f = 0; f < 128; f += 2) {
            float2 x2 = *(const float2*)&xp[f];
            unsigned long long w0 = *(const unsigned long long*)&wp[f * 64];
            unsigned long long w1v = *(const unsigned long long*)&wp[(f + 1) * 64];
            acc0 = fma2(pk2(x2.x, x2.x), w0, acc0);
            acc1 = fma2(pk2(x2.y, x2.y), w1v, acc1);
        }
        float v0, v1;
        upk2(add2(acc0, acc1), v0, v1);
        *(float2*)&g_hp2[(size_t)(b * 512 + n) * 64 + 2 * lane] =
            make_float2(v0, v1);
        float th0 = tanhf(v0), th1 = tanhf(v1);
        float ps = th0 * a0v + th1 * a1v;
        float pd = th0 * d0v + th1 * d1v;
        #pragma unroll
        for (int off = 16; off; off >>= 1) {
            ps += __shfl_xor_sync(0xffffffffu, ps, off);
            pd += __shfl_xor_sync(0xffffffffu, pd, off);
        }
        if (lane == 0) {
            g_as2[b * 512 + n] = ps;
            g_ad2[b * 512 + n] = pd;
        }
    }
}

// ---------------- K4: layer-2 rows 0/1 + MLP + log_softmax ----------------
__global__ void __launch_bounds__(512) k_final(
    const float* __restrict__ b2,
    const float* __restrict__ fc1_w, const float* __restrict__ fc1_b,
    const float* __restrict__ fc2_w, const float* __restrict__ fc2_b,
    const float* __restrict__ fc3_w, const float* __restrict__ fc3_b,
    float* __restrict__ out_scores, float* __restrict__ out_vsm)
{
    __shared__ float att2[2 * 512];
    __shared__ float inv[2];
    __shared__ float part[512];
    __shared__ float xrow[128];
    __shared__ float vsm[64], v1[192], v2s[64];
    __shared__ float red[32];
    __shared__ float sc[2];
    int tid = threadIdx.x, b = blockIdx.x;
    int lane = tid & 31, wid = tid >> 5;

    float ad2 = g_ad2[b * 512 + tid];
    unsigned wrd  = g_bits[b * 8192 + (tid >> 5)];
    unsigned wrd1 = g_bits[b * 8192 + 16 + (tid >> 5)];
    float as0 = g_as2[b * 512 + 0], as1 = g_as2[b * 512 + 1];
    float s0 = as0 + ad2, s1 = as1 + ad2;
    float e0 = ((wrd  >> lane) & 1u) ? expf(s0 >= 0.f ? s0 : 0.2f * s0) : 0.f;
    float e1 = ((wrd1 >> lane) & 1u) ? expf(s1 >= 0.f ? s1 : 0.2f * s1) : 0.f;
    att2[tid] = e0;
    att2[512 + tid] = e1;
    float p0 = e0, p1 = e1;
    #pragma unroll
    for (int off = 16; off; off >>= 1) {
        p0 += __shfl_xor_sync(0xffffffffu, p0, off);
        p1 += __shfl_xor_sync(0xffffffffu, p1, off);
    }
    if (lane == 0) { red[wid] = p0; red[16 + wid] = p1; }
    __syncthreads();
    if (tid < 32) {
        float v = red[tid];
        #pragma unroll
        for (int off = 8; off; off >>= 1)
            v += __shfl_xor_sync(0xffffffffu, v, off);
        if (tid == 0)  inv[0] = 1.f / v;
        if (tid == 16) inv[1] = 1.f / v;
    }
    __syncthreads();

    {
        int r = tid >> 8, o = tid & 63, sub = (tid >> 6) & 3;
        const float* hp = g_hp2 + (size_t)b * 32768 + o;
        const float* av = att2 + r * 512 + sub * 128;
        float a0 = 0.f, a1 = 0.f, a2 = 0.f, a3 = 0.f;
        int mb = sub * 128;
        #pragma unroll 4
        for (int k = 0; k < 128; k += 4) {
            a0 = fmaf(av[k],     hp[(size_t)(mb + k) * 64],     a0);
            a1 = fmaf(av[k + 1], hp[(size_t)(mb + k + 1) * 64], a1);
            a2 = fmaf(av[k + 2], hp[(size_t)(mb + k + 2) * 64], a2);
            a3 = fmaf(av[k + 3], hp[(size_t)(mb + k + 3) * 64], a3);
        }
        part[tid] = (a0 + a1) + (a2 + a3);
    }
    __syncthreads();
    if (tid < 128) {
        int r = tid >> 6, o = tid & 63;
        float x = (part[r * 256 + o] + part[r * 256 + 64 + o] +
                   part[r * 256 + 128 + o] + part[r * 256 + 192 + o]) * inv[r] + b2[o];
        xrow[tid] = x > 0.f ? x : expm1f(x);
    }
    __syncthreads();
    if (tid < 64) {
        float vv = xrow[tid] * xrow[64 + tid];
        vsm[tid] = vv;
        out_vsm[b * 64 + tid] = vv;
    }
    __syncthreads();
    if (tid < 192) {
        float acc = fc1_b[tid];
        for (int f = 0; f < 64; f++) acc = fmaf(vsm[f], fc1_w[f * 192 + tid], acc);
        v1[tid] = fmaxf(acc, 0.f);
    }
    __syncthreads();
    if (tid < 64) {
        float acc = fc2_b[tid];
        for (int f = 0; f < 192; f++) acc = fmaf(v1[f], fc2_w[f * 64 + tid], acc);
        v2s[tid] = fmaxf(acc, 0.f);
    }
    __syncthreads();
    if (tid < 2) {
        float acc = fc3_b[tid];
        for (int f = 0; f < 64; f++) acc = fmaf(v2s[f], fc3_w[f * 2 + tid], acc);
        sc[tid] = acc;
    }
    __syncthreads();
    if (tid < 2) {
        float m = fmaxf(sc[0], sc[1]);
        float lse = m + logf(expf(sc[0] - m) + expf(sc[1] - m));
        out_scores[b * 2 + tid] = sc[tid] - lse;
    }
}

// ---------------- launch ----------------
extern "C" void kernel_launch(void* const* d_in, const int* in_sizes, int n_in,
                              void* d_out, int out_size) {
    (void)in_sizes; (void)n_in; (void)out_size;
    const float* features = (const float*)d_in[0];
    const int*   adj      = (const int*)  d_in[1];
    const float* line_emb = (const float*)d_in[5];
    const int*   v_types  = (const int*)  d_in[6];
    const float* w1       = (const float*)d_in[7];
    const float* a_src1   = (const float*)d_in[8];
    const float* a_dst1   = (const float*)d_in[9];
    const float* b1       = (const float*)d_in[10];
    const float* w2       = (const float*)d_in[11];
    const float* a_src2   = (const float*)d_in[12];
    const float* a_dst2   = (const float*)d_in[13];
    const float* b2       = (const float*)d_in[14];
    const float* fc1_w    = (const float*)d_in[15];
    const float* fc1_b    = (const float*)d_in[16];
    const float* fc2_w    = (const float*)d_in[17];
    const float* fc2_b    = (const float*)d_in[18];
    const float* fc3_w    = (const float*)d_in[19];
    const float* fc3_b    = (const float*)d_in[20];

    float* out   = (float*)d_out;
    float* vsm   = out + 64;       // v_sim_mul [32,64]
    float* attn1 = out + 2112;     // attn1 [32,8,512,512]

    cudaFuncSetAttribute(k_proj1, cudaFuncAttributeMaxDynamicSharedMemorySize, 67000);
    cudaFuncSetAttribute(k_fuse,  cudaFuncAttributeMaxDynamicSharedMemorySize, 58000);
    cudaFuncSetAttribute(k_proj2, cudaFuncAttributeMaxDynamicSharedMemorySize, 132000);

    k_pack <<<32768, 256>>>(adj);
    k_proj1<<<dim3(8, 2, 32), 512, 66304>>>(features, line_emb, v_types, w1, a_src1, a_dst1);
    k_fuse <<<dim3(2, 8, 32), 128, 57408>>>(b1, attn1);
    k_proj2<<<dim3(8, 32), 512, 131840>>>(v_types, w2, a_src2, a_dst2);
    k_final<<<32, 512>>>(b2, fc1_w, fc1_b, fc2_w, fc2_b, fc3_w, fc3_b, out, vsm);
}